// round 11
// baseline (speedup 1.0000x reference)
#include <cuda_runtime.h>
#include <cuda_bf16.h>
#include <math.h>
#include <cstdint>

#define B_SZ  4096
#define DIN   256
#define NOUT  32
#define MM    128
#define NH    2
#define HOC   (NH*NOUT)
#define JIT   1e-4f
#define TRILN (MM*(MM+1)/2)
#define D2CUT 170.0f

// ---------------- scratch ----------------
__device__ float g_sf2v[NH];
__device__ float g_x2[NH*B_SZ];
__device__ float g_z2[HOC*MM];
__device__ float g_cv[HOC*MM];
__device__ __align__(16) __nv_bfloat16 g_xb[NH*B_SZ*DIN];
__device__ __align__(16) __nv_bfloat16 g_zb[HOC*MM*DIN];
__device__ __align__(16) __nv_bfloat16 g_Qb[HOC*MM*MM];

// ---------------- helpers ----------------
__device__ __forceinline__ uint32_t smem_u32(const void* p){
  uint32_t a;
  asm("{ .reg .u64 t; cvta.to.shared.u64 t, %1; cvt.u32.u64 %0, t; }" : "=r"(a) : "l"(p));
  return a;
}
__device__ __forceinline__ void ldsm4(uint32_t addr, uint32_t* r){
  asm volatile("ldmatrix.sync.aligned.m8n8.x4.shared.b16 {%0,%1,%2,%3}, [%4];"
    : "=r"(r[0]),"=r"(r[1]),"=r"(r[2]),"=r"(r[3]) : "r"(addr));
}
__device__ __forceinline__ void mma16816(float* c, const uint32_t* a, const uint32_t* b){
  asm volatile("mma.sync.aligned.m16n8k16.row.col.f32.bf16.bf16.f32 "
    "{%0,%1,%2,%3}, {%4,%5,%6,%7}, {%8,%9}, {%0,%1,%2,%3};"
    : "+f"(c[0]),"+f"(c[1]),"+f"(c[2]),"+f"(c[3])
    : "r"(a[0]),"r"(a[1]),"r"(a[2]),"r"(a[3]), "r"(b[0]),"r"(b[1]));
}
#define CP16(dst, src) asm volatile("cp.async.cg.shared.global [%0], [%1], 16;" :: "r"(dst), "l"(src))
#define CP_COMMIT()    asm volatile("cp.async.commit_group;" ::: "memory")
#define CP_WAIT(n)     asm volatile("cp.async.wait_group %0;" :: "n"(n) : "memory")

__device__ __forceinline__ uint32_t pack_bf16x2(float lo, float hi){
  uint32_t r;
  asm("cvt.rn.satfinite.bf16x2.f32 %0, %1, %2;" : "=r"(r) : "f"(hi), "f"(lo));
  return r;
}
__device__ __forceinline__ float rbf(float sf2, float d2){
  return (d2 < D2CUT) ? sf2*__expf(-0.5f*d2) : 0.f;
}

#define SP2    80       // z-stage pitch bytes (32 bf16 + 16B pad)
#define XSTB   10240    // one z-stage buffer: 128*80
#define KPITCH 272      // 128-col bf16 tile pitch
#define XP     528      // resident x tile pitch (256 bf16 + 16B pad)
#define G      4        // ho's per k_main block

// 128x128x128 bf16 block GEMM from KPITCH tiles
__device__ __forceinline__ void mm128(uint32_t aBase, uint32_t bBase,
                                      int wr, int wc, int l15, int lh,
                                      float acc[16][4]){
  uint32_t aB0 = aBase + (wr*32 + l15)*KPITCH + lh*16;
  uint32_t bB0 = bBase + (wc*64 + l15)*KPITCH + lh*16;
  #pragma unroll
  for (int ks=0;ks<8;ks++){
    uint32_t af[2][4], bt[4], bfr[8][2];
    #pragma unroll
    for (int mt=0;mt<2;mt++) ldsm4(aB0 + ks*32 + mt*16*KPITCH, af[mt]);
    #pragma unroll
    for (int nn=0;nn<4;nn++){
      ldsm4(bB0 + ks*32 + nn*16*KPITCH, bt);
      bfr[nn*2][0]=bt[0]; bfr[nn*2][1]=bt[2];
      bfr[nn*2+1][0]=bt[1]; bfr[nn*2+1][1]=bt[3];
    }
    #pragma unroll
    for (int mt=0;mt<2;mt++)
      #pragma unroll
      for (int nf=0;nf<8;nf++)
        mma16816(acc[mt*8+nf], af[mt], bfr[nf]);
  }
}

// one K=32 chunk, both operands SP2 pitch (k_factor)
__device__ __forceinline__ void chunk32(uint32_t aB, uint32_t bB, float acc[16][4]){
  #pragma unroll
  for (int ks=0;ks<2;ks++){
    uint32_t af[2][4], bt[4], bfr[8][2];
    #pragma unroll
    for (int mt=0;mt<2;mt++) ldsm4(aB + ks*32 + mt*16*SP2, af[mt]);
    #pragma unroll
    for (int nn=0;nn<4;nn++){
      ldsm4(bB + ks*32 + nn*16*SP2, bt);
      bfr[nn*2][0]=bt[0]; bfr[nn*2][1]=bt[2];
      bfr[nn*2+1][0]=bt[1]; bfr[nn*2+1][1]=bt[3];
    }
    #pragma unroll
    for (int mt=0;mt<2;mt++)
      #pragma unroll
      for (int nf=0;nf<8;nf++)
        mma16816(acc[mt*8+nf], af[mt], bfr[nf]);
  }
}

// one K=32 chunk: A from resident x (XP pitch), B from z ring (SP2 pitch)
__device__ __forceinline__ void chunk32x(uint32_t aB, uint32_t bB, float acc[16][4]){
  #pragma unroll
  for (int ks=0;ks<2;ks++){
    uint32_t af[2][4], bt[4], bfr[8][2];
    #pragma unroll
    for (int mt=0;mt<2;mt++) ldsm4(aB + ks*32 + mt*16*XP, af[mt]);
    #pragma unroll
    for (int nn=0;nn<4;nn++){
      ldsm4(bB + ks*32 + nn*16*SP2, bt);
      bfr[nn*2][0]=bt[0]; bfr[nn*2][1]=bt[2];
      bfr[nn*2+1][0]=bt[1]; bfr[nn*2+1][1]=bt[3];
    }
    #pragma unroll
    for (int mt=0;mt<2;mt++)
      #pragma unroll
      for (int nf=0;nf<8;nf++)
        mma16816(acc[mt*8+nf], af[mt], bfr[nf]);
  }
}

// ---------------- prep: shared scal table, 4 rows/block ----------------
__global__ void k_prep(const float* __restrict__ x, const float* __restrict__ z,
                       const float* __restrict__ theta){
  __shared__ float sscal[256];
  __shared__ float sw[8];
  int tid = threadIdx.x;
  int lane = tid & 31, wid = tid >> 5;
  int row0 = blockIdx.x*4;
  // h uniform across the 4 rows of this block (boundaries divisible by 4)
  int hblk = (row0 < NH*B_SZ) ? (row0 / B_SZ)
                              : ((row0 - NH*B_SZ) / (NOUT*MM));
  sscal[tid] = expf(-theta[hblk*(DIN+1) + 1 + tid]);
  if (blockIdx.x == 0 && tid < NH) g_sf2v[tid] = expf(theta[tid*(DIN+1)]);
  __syncthreads();

  int rloc = tid >> 6;
  int col  = (tid & 63) << 2;
  int row  = row0 + rloc;

  const float* src; __nv_bfloat16* dst;
  if (row < NH*B_SZ){
    int b = row - hblk*B_SZ;
    src = x + (size_t)b*DIN;
    dst = g_xb + (size_t)row*DIN;
  } else {
    int id = row - NH*B_SZ;
    int om = id % (NOUT*MM);
    src = z + (size_t)om*DIN;
    dst = g_zb + (size_t)id*DIN;
  }
  float4 xv = *(const float4*)(src + col);
  float v0 = xv.x * sscal[col];
  float v1 = xv.y * sscal[col+1];
  float v2 = xv.z * sscal[col+2];
  float v3 = xv.w * sscal[col+3];
  uint2 pk = make_uint2(pack_bf16x2(v0,v1), pack_bf16x2(v2,v3));
  *(uint2*)(dst + col) = pk;

  float p = v0*v0 + v1*v1 + v2*v2 + v3*v3;
  #pragma unroll
  for (int o=16;o;o>>=1) p += __shfl_down_sync(0xffffffffu, p, o);
  if (lane == 0) sw[wid] = p;
  __syncthreads();
  if (tid < 4){
    float t = sw[2*tid] + sw[2*tid+1];
    int r = row0 + tid;
    if (r < NH*B_SZ) g_x2[r] = t; else g_z2[r - NH*B_SZ] = t;
  }
}

// ============ k_factor (unchanged from R10) ============
#define N_KB   0
#define N_XB   34816
#define N_YB   69632
#define N_UM   104448
#define N_PC   104960
#define N_TOT  105984

__global__ __launch_bounds__(256) void k_factor(const float* __restrict__ u_mean,
                                                const float* __restrict__ u_tril){
  extern __shared__ char smc[];
  uint32_t sb = smem_u32(smc);
  float* um = (float*)(smc + N_UM);
  float* pc = (float*)(smc + N_PC);

  int ho = blockIdx.x;
  int h = ho / NOUT, o = ho % NOUT;
  int tid = threadIdx.x;
  int wid = tid >> 5, lane = tid & 31;
  int wr = wid >> 1, wc = wid & 1;
  int l15 = lane & 15, lh = lane >> 4;
  int lane4 = lane >> 2, lpair = (lane & 3)*2;

  const __nv_bfloat16* zb = g_zb + (size_t)ho*MM*DIN;
  float sf2 = g_sf2v[h];
  float dK  = sf2 + JIT;
  float c0  = 1.0f / dK;

  if (tid < MM) um[tid] = u_mean[o*MM + tid];

  int offdiag_nz = 0;
  {
    uint32_t zs_base[3];
    #pragma unroll
    for (int s=0;s<3;s++) zs_base[s] = sb + N_YB + s*XSTB;
    int row0 = tid >> 2, q0 = tid & 3;
    int row1 = (tid+256) >> 2, q1 = (tid+256) & 3;
    #pragma unroll
    for (int s=0;s<2;s++){
      CP16(zs_base[s] + row0*SP2 + q0*16, zb + (size_t)row0*DIN + s*32 + q0*8);
      CP16(zs_base[s] + row1*SP2 + q1*16, zb + (size_t)row1*DIN + s*32 + q1*8);
      CP_COMMIT();
    }

    float acc[16][4];
    #pragma unroll
    for (int i=0;i<16;i++)
      #pragma unroll
      for (int j=0;j<4;j++) acc[i][j]=0.f;

    uint32_t aoff = (wr*32 + l15)*SP2 + lh*16;
    uint32_t boff = (wc*64 + l15)*SP2 + lh*16;
    #pragma unroll 1
    for (int c=0;c<8;c++){
      if (c == 7) { CP_WAIT(0); } else { CP_WAIT(1); }
      __syncthreads();
      int cur = c % 3;
      chunk32(zs_base[cur] + aoff, zs_base[cur] + boff, acc);
      if (c < 6){
        int nx = (c+2)%3;
        CP16(zs_base[nx] + row0*SP2 + q0*16, zb + (size_t)row0*DIN + (c+2)*32 + q0*8);
        CP16(zs_base[nx] + row1*SP2 + q1*16, zb + (size_t)row1*DIN + (c+2)*32 + q1*8);
        CP_COMMIT();
      }
    }

    #pragma unroll
    for (int mt=0;mt<2;mt++){
      int r0 = wr*32 + mt*16 + lane4;
      int r1 = r0 + 8;
      float z20 = g_z2[ho*MM+r0], z21 = g_z2[ho*MM+r1];
      #pragma unroll
      for (int nf=0;nf<8;nf++){
        int cb = wc*64 + nf*8 + lpair;
        float zc0 = g_z2[ho*MM+cb], zc1 = g_z2[ho*MM+cb+1];
        float* a4 = acc[mt*8+nf];
        float v00 = (r0==cb  ) ? dK : rbf(sf2, fmaxf(z20+zc0-2.f*a4[0],0.f));
        float v01 = (r0==cb+1) ? dK : rbf(sf2, fmaxf(z20+zc1-2.f*a4[1],0.f));
        float v10 = (r1==cb  ) ? dK : rbf(sf2, fmaxf(z21+zc0-2.f*a4[2],0.f));
        float v11 = (r1==cb+1) ? dK : rbf(sf2, fmaxf(z21+zc1-2.f*a4[3],0.f));
        if ((r0!=cb   && v00!=0.f) || (r0!=cb+1 && v01!=0.f) ||
            (r1!=cb   && v10!=0.f) || (r1!=cb+1 && v11!=0.f)) offdiag_nz = 1;
        *(uint32_t*)(smc + N_KB + r0*KPITCH + cb*2) = pack_bf16x2(v00,v01);
        *(uint32_t*)(smc + N_KB + r1*KPITCH + cb*2) = pack_bf16x2(v10,v11);
        float x00 = (r0==cb  ) ? c0 : 0.f;
        float x01 = (r0==cb+1) ? c0 : 0.f;
        float x10 = (r1==cb  ) ? c0 : 0.f;
        float x11 = (r1==cb+1) ? c0 : 0.f;
        *(uint32_t*)(smc + N_XB + r0*KPITCH + cb*2) = pack_bf16x2(x00,x01);
        *(uint32_t*)(smc + N_XB + r1*KPITCH + cb*2) = pack_bf16x2(x10,x11);
      }
    }
  }

  int any = __syncthreads_or(offdiag_nz);

  if (!any){
    if (tid < MM) g_cv[ho*MM + tid] = c0 * um[tid];
    {
      const float* Lv = u_tril + (size_t)o*TRILN;
      for (int it=0; it<32; it++){
        int idx = tid + it*256;
        int j = idx & 127, kp = (idx >> 7)*2;
        float v0 = (kp   >= j) ? c0*Lv[(kp*(kp+1))/2 + j] : 0.f;
        float v1 = (kp+1 >= j) ? c0*Lv[((kp+1)*(kp+2))/2 + j] : 0.f;
        *(uint32_t*)(smc + N_KB + j*KPITCH + kp*2) = pack_bf16x2(v0, v1);
      }
    }
    __syncthreads();
    float acc[16][4];
    #pragma unroll
    for (int i=0;i<16;i++)
      #pragma unroll
      for (int j=0;j<4;j++) acc[i][j]=0.f;
    mm128(sb + N_KB, sb + N_KB, wr, wc, l15, lh, acc);
    __nv_bfloat16* Qg = g_Qb + (size_t)ho*MM*MM;
    #pragma unroll
    for (int mt=0;mt<2;mt++){
      int r0 = wr*32 + mt*16 + lane4;
      int r1 = r0 + 8;
      #pragma unroll
      for (int nf=0;nf<8;nf++){
        int cb = wc*64 + nf*8 + lpair;
        float* a4 = acc[mt*8+nf];
        float q00 = ((r0==cb  ) ? c0 : 0.f) - a4[0];
        float q01 = ((r0==cb+1) ? c0 : 0.f) - a4[1];
        float q10 = ((r1==cb  ) ? c0 : 0.f) - a4[2];
        float q11 = ((r1==cb+1) ? c0 : 0.f) - a4[3];
        *(uint32_t*)&Qg[(size_t)r0*MM + cb] = pack_bf16x2(q00,q01);
        *(uint32_t*)&Qg[(size_t)r1*MM + cb] = pack_bf16x2(q10,q11);
      }
    }
    return;
  }

  // slow path: Newton-Schulz x2
  #pragma unroll 1
  for (int it=0; it<2; it++){
    __syncthreads();
    {
      float acc[16][4];
      #pragma unroll
      for (int i=0;i<16;i++)
        #pragma unroll
        for (int j=0;j<4;j++) acc[i][j]=0.f;
      mm128(sb + N_KB, sb + N_XB, wr, wc, l15, lh, acc);
      #pragma unroll
      for (int mt=0;mt<2;mt++){
        int r0 = wr*32 + mt*16 + lane4;
        int r1 = r0 + 8;
        #pragma unroll
        for (int nf=0;nf<8;nf++){
          int cb = wc*64 + nf*8 + lpair;
          float* a4 = acc[mt*8+nf];
          *(uint32_t*)(smc + N_YB + r0*KPITCH + cb*2) = pack_bf16x2(a4[0],a4[1]);
          *(uint32_t*)(smc + N_YB + r1*KPITCH + cb*2) = pack_bf16x2(a4[2],a4[3]);
        }
      }
    }
    __syncthreads();
    {
      float acc[16][4];
      #pragma unroll
      for (int i=0;i<16;i++)
        #pragma unroll
        for (int j=0;j<4;j++) acc[i][j]=0.f;
      mm128(sb + N_XB, sb + N_YB, wr, wc, l15, lh, acc);
      __syncthreads();
      float c_acc[4] = {0.f,0.f,0.f,0.f};
      #pragma unroll
      for (int mt=0;mt<2;mt++){
        int r0 = wr*32 + mt*16 + lane4;
        int r1 = r0 + 8;
        #pragma unroll
        for (int nf=0;nf<8;nf++){
          int cb = wc*64 + nf*8 + lpair;
          uint32_t p0 = *(const uint32_t*)(smc + N_XB + r0*KPITCH + cb*2);
          uint32_t p1 = *(const uint32_t*)(smc + N_XB + r1*KPITCH + cb*2);
          __nv_bfloat162 h0 = *reinterpret_cast<__nv_bfloat162*>(&p0);
          __nv_bfloat162 h1 = *reinterpret_cast<__nv_bfloat162*>(&p1);
          float* a4 = acc[mt*8+nf];
          float n00 = 2.f*__low2float(h0)  - a4[0];
          float n01 = 2.f*__high2float(h0) - a4[1];
          float n10 = 2.f*__low2float(h1)  - a4[2];
          float n11 = 2.f*__high2float(h1) - a4[3];
          *(uint32_t*)(smc + N_XB + r0*KPITCH + cb*2) = pack_bf16x2(n00,n01);
          *(uint32_t*)(smc + N_XB + r1*KPITCH + cb*2) = pack_bf16x2(n10,n11);
          if (it == 1){
            float u0 = um[cb], u1 = um[cb+1];
            c_acc[mt*2+0] += n00*u0 + n01*u1;
            c_acc[mt*2+1] += n10*u0 + n11*u1;
          }
        }
      }
      if (it == 1){
        #pragma unroll
        for (int u=0;u<4;u++){
          float v = c_acc[u];
          v += __shfl_xor_sync(0xffffffffu, v, 1);
          v += __shfl_xor_sync(0xffffffffu, v, 2);
          if ((lane & 3) == 0){
            int row = wr*32 + (u>>1)*16 + (u&1)*8 + lane4;
            pc[wc*128 + row] = v;
          }
        }
      }
    }
  }
  __syncthreads();
  if (tid < MM) g_cv[ho*MM + tid] = pc[tid] + pc[128+tid];

  {
    const float* Lv = u_tril + (size_t)o*TRILN;
    for (int it=0; it<32; it++){
      int idx = tid + it*256;
      int j = idx & 127, kp = (idx >> 7)*2;
      float v0 = (kp   >= j) ? Lv[(kp*(kp+1))/2 + j] : 0.f;
      float v1 = (kp+1 >= j) ? Lv[((kp+1)*(kp+2))/2 + j] : 0.f;
      *(uint32_t*)(smc + N_KB + j*KPITCH + kp*2) = pack_bf16x2(v0, v1);
    }
  }
  __syncthreads();

  {
    float acc[16][4];
    #pragma unroll
    for (int i=0;i<16;i++)
      #pragma unroll
      for (int j=0;j<4;j++) acc[i][j]=0.f;
    mm128(sb + N_XB, sb + N_KB, wr, wc, l15, lh, acc);
    __syncthreads();
    #pragma unroll
    for (int mt=0;mt<2;mt++){
      int r0 = wr*32 + mt*16 + lane4;
      int r1 = r0 + 8;
      #pragma unroll
      for (int nf=0;nf<8;nf++){
        int cb = wc*64 + nf*8 + lpair;
        float* a4 = acc[mt*8+nf];
        *(uint32_t*)(smc + N_YB + r0*KPITCH + cb*2) = pack_bf16x2(a4[0],a4[1]);
        *(uint32_t*)(smc + N_YB + r1*KPITCH + cb*2) = pack_bf16x2(a4[2],a4[3]);
      }
    }
  }
  __syncthreads();

  {
    float acc[16][4];
    #pragma unroll
    for (int i=0;i<16;i++)
      #pragma unroll
      for (int j=0;j<4;j++) acc[i][j]=0.f;
    mm128(sb + N_YB, sb + N_YB, wr, wc, l15, lh, acc);
    __nv_bfloat16* Qg = g_Qb + (size_t)ho*MM*MM;
    #pragma unroll
    for (int mt=0;mt<2;mt++){
      int r0 = wr*32 + mt*16 + lane4;
      int r1 = r0 + 8;
      #pragma unroll
      for (int nf=0;nf<8;nf++){
        int cb = wc*64 + nf*8 + lpair;
        uint32_t p0 = *(const uint32_t*)(smc + N_XB + r0*KPITCH + cb*2);
        uint32_t p1 = *(const uint32_t*)(smc + N_XB + r1*KPITCH + cb*2);
        __nv_bfloat162 h0 = *reinterpret_cast<__nv_bfloat162*>(&p0);
        __nv_bfloat162 h1 = *reinterpret_cast<__nv_bfloat162*>(&p1);
        float* a4 = acc[mt*8+nf];
        *(uint32_t*)&Qg[(size_t)r0*MM + cb] = pack_bf16x2(__low2float(h0)-a4[0], __high2float(h0)-a4[1]);
        *(uint32_t*)&Qg[(size_t)r1*MM + cb] = pack_bf16x2(__low2float(h1)-a4[2], __high2float(h1)-a4[3]);
      }
    }
  }
}

// ============ k_main: resident x tile, G=4 ho per block ============
#define OFF_X2   0        // 512
#define OFF_Z2   512      // 512
#define OFF_CS   1024     // 512
#define OFF_PMU  1536     // 1024
#define OFF_PVAR 2560     // 1024
#define OFF_XR   3584     // 128*528 = 67584 -> 71168
#define OFF_ZR   71168    // 3*10240 = 30720 -> 101888
#define OFF_KUF  101888   // 34816 -> 136704
#define OFF_Q    136704   // 34816 -> 171520
#define SMEM_MAIN 171520

__global__ __launch_bounds__(256,1) void k_main(float* __restrict__ out){
  extern __shared__ char smc[];
  uint32_t sb = smem_u32(smc);
  float* sx2 = (float*)(smc + OFF_X2);
  float* sz2 = (float*)(smc + OFF_Z2);
  float* cs  = (float*)(smc + OFF_CS);
  float* pmu = (float*)(smc + OFF_PMU);
  float* pvar= (float*)(smc + OFF_PVAR);

  int ho0 = blockIdx.y * G;
  int h   = ho0 / NOUT;
  int b0  = blockIdx.x * MM;
  int tid = threadIdx.x;
  int wid = tid >> 5, lane = tid & 31;
  int wr = wid >> 1, wc = wid & 1;
  int l15 = lane & 15, lh = lane >> 4;
  int lane4 = lane >> 2, lpair = (lane & 3)*2;

  if (tid < MM) sx2[tid] = g_x2[h*B_SZ + b0 + tid];

  const __nv_bfloat16* xb = g_xb + ((size_t)h*B_SZ + b0)*DIN;
  float sf2 = g_sf2v[h];

  uint32_t zr_base[3];
  #pragma unroll
  for (int s=0;s<3;s++) zr_base[s] = sb + OFF_ZR + s*XSTB;
  int prow = tid >> 1, pq = tid & 1;   // z stage: 2 CP16 per thread... (128 rows x 4 segs = 512 CP16 / 256 thr = 2)
  int prow2 = (tid+256) >> 2;          // unused pattern below; use 4-seg mapping
  (void)prow; (void)pq; (void)prow2;

  // group 0: resident x (4096 CP16) + z chunk 0 ; group 1: z chunk 1
  {
    #pragma unroll
    for (int it=0; it<16; it++){
      int seg = tid + it*256;
      int r = seg >> 5, q = seg & 31;
      CP16(sb + OFF_XR + r*XP + q*16, xb + (size_t)r*DIN + q*8);
    }
    const __nv_bfloat16* zb0 = g_zb + (size_t)ho0*MM*DIN;
    int r0 = tid >> 2, q0 = tid & 3;
    int r1 = (tid+256) >> 2, q1 = (tid+256) & 3;
    CP16(zr_base[0] + r0*SP2 + q0*16, zb0 + (size_t)r0*DIN + 0 + q0*8);
    CP16(zr_base[0] + r1*SP2 + q1*16, zb0 + (size_t)r1*DIN + 0 + q1*8);
    CP_COMMIT();
    CP16(zr_base[1] + r0*SP2 + q0*16, zb0 + (size_t)r0*DIN + 32 + q0*8);
    CP16(zr_base[1] + r1*SP2 + q1*16, zb0 + (size_t)r1*DIN + 32 + q1*8);
    CP_COMMIT();
  }

  uint32_t aoffA = (wr*32 + l15)*XP + lh*16;
  uint32_t boffA = (wc*64 + l15)*SP2 + lh*16;
  int zr0 = tid >> 2, zq0 = tid & 3;
  int zr1 = (tid+256) >> 2, zq1 = (tid+256) & 3;

  #pragma unroll 1
  for (int g=0; g<G; g++){
    int ho = ho0 + g;
    if (tid < MM) sz2[tid] = g_z2[ho*MM + tid];

    float acc[16][4];
    #pragma unroll
    for (int i=0;i<16;i++)
      #pragma unroll
      for (int j=0;j<4;j++) acc[i][j]=0.f;

    #pragma unroll 1
    for (int c=0;c<8;c++){
      int t = g*8 + c;
      CP_WAIT(1);
      __syncthreads();
      chunk32x(sb + OFF_XR + aoffA + c*64, zr_base[t%3] + boffA, acc);
      int tn = t + 2;
      if (tn < G*8){
        const __nv_bfloat16* zbn = g_zb + (size_t)(ho0 + (tn>>3))*MM*DIN;
        int cn = tn & 7;
        CP16(zr_base[tn%3] + zr0*SP2 + zq0*16, zbn + (size_t)zr0*DIN + cn*32 + zq0*8);
        CP16(zr_base[tn%3] + zr1*SP2 + zq1*16, zbn + (size_t)zr1*DIN + cn*32 + zq1*8);
      }
      CP_COMMIT();   // uniform one-group-per-iteration (may be empty)
    }

    // epilogue: kuf values into acc (in place), zero-vote
    uint32_t nzbits = 0;
    #pragma unroll
    for (int mt=0;mt<2;mt++){
      int r0 = wr*32 + mt*16 + lane4;
      int r1 = r0 + 8;
      float x20 = sx2[r0], x21 = sx2[r1];
      #pragma unroll
      for (int nf=0;nf<8;nf++){
        int cb = wc*64 + nf*8 + lpair;
        float z20 = sz2[cb], z21 = sz2[cb+1];
        float* a4 = acc[mt*8+nf];
        a4[0] = rbf(sf2, fmaxf(x20 + z20 - 2.f*a4[0], 0.f));
        a4[1] = rbf(sf2, fmaxf(x20 + z21 - 2.f*a4[1], 0.f));
        a4[2] = rbf(sf2, fmaxf(x21 + z20 - 2.f*a4[2], 0.f));
        a4[3] = rbf(sf2, fmaxf(x21 + z21 - 2.f*a4[3], 0.f));
        nzbits |= __float_as_uint(a4[0]) | __float_as_uint(a4[1]) |
                  __float_as_uint(a4[2]) | __float_as_uint(a4[3]);
      }
    }

    int any = __syncthreads_or((int)nzbits);

    if (!any){
      // kuf == 0 exactly: mu = 0, var = sf2
      if (tid < MM){
        size_t base = (size_t)ho*B_SZ + b0 + tid;
        out[base] = 0.f;
        out[(size_t)HOC*B_SZ + base] = sf2;
      }
      continue;
    }

    // ---- rare nonzero path ----
    if (tid < MM) cs[tid] = g_cv[ho*MM + tid];
    #pragma unroll
    for (int mt=0;mt<2;mt++){
      int r0 = wr*32 + mt*16 + lane4;
      int r1 = r0 + 8;
      #pragma unroll
      for (int nf=0;nf<8;nf++){
        int cb = wc*64 + nf*8 + lpair;
        float* a4 = acc[mt*8+nf];
        *(uint32_t*)(smc + OFF_KUF + r0*KPITCH + cb*2) = pack_bf16x2(a4[0],a4[1]);
        *(uint32_t*)(smc + OFF_KUF + r1*KPITCH + cb*2) = pack_bf16x2(a4[2],a4[3]);
      }
    }
    {
      const __nv_bfloat16* Qg = g_Qb + (size_t)ho*MM*MM;
      #pragma unroll
      for (int it=0; it<8; it++){
        int t = tid + it*256;
        int r = t >> 4, cg = t & 15;
        uint4 v = *(const uint4*)(Qg + (size_t)r*MM + cg*8);
        *(uint4*)(smc + OFF_Q + r*KPITCH + cg*16) = v;
      }
    }
    __syncthreads();

    // mu partials from kv (still in acc) + cs
    {
      float mu_acc[4] = {0.f,0.f,0.f,0.f};
      #pragma unroll
      for (int mt=0;mt<2;mt++){
        #pragma unroll
        for (int nf=0;nf<8;nf++){
          int cb = wc*64 + nf*8 + lpair;
          float* a4 = acc[mt*8+nf];
          float c0 = cs[cb], c1 = cs[cb+1];
          mu_acc[mt*2+0] += a4[0]*c0 + a4[1]*c1;
          mu_acc[mt*2+1] += a4[2]*c0 + a4[3]*c1;
        }
      }
      #pragma unroll
      for (int u=0;u<4;u++){
        float v = mu_acc[u];
        v += __shfl_xor_sync(0xffffffffu, v, 1);
        v += __shfl_xor_sync(0xffffffffu, v, 2);
        if ((lane & 3) == 0){
          int row = wr*32 + (u>>1)*16 + (u&1)*8 + lane4;
          pmu[wc*128 + row] = v;
        }
      }
    }

    // Phase B: y = kuf @ Q^T
    #pragma unroll
    for (int i=0;i<16;i++)
      #pragma unroll
      for (int j=0;j<4;j++) acc[i][j]=0.f;
    mm128(sb + OFF_KUF, sb + OFF_Q, wr, wc, l15, lh, acc);

    {
      float v_acc[4] = {0.f,0.f,0.f,0.f};
      #pragma unroll
      for (int mt=0;mt<2;mt++){
        int r0 = wr*32 + mt*16 + lane4;
        int r1 = r0 + 8;
        #pragma unroll
        for (int nf=0;nf<8;nf++){
          int cb = wc*64 + nf*8 + lpair;
          uint32_t p0 = *(const uint32_t*)(smc + OFF_KUF + r0*KPITCH + cb*2);
          uint32_t p1 = *(const uint32_t*)(smc + OFF_KUF + r1*KPITCH + cb*2);
          __nv_bfloat162 h0 = *reinterpret_cast<__nv_bfloat162*>(&p0);
          __nv_bfloat162 h1 = *reinterpret_cast<__nv_bfloat162*>(&p1);
          float* a4 = acc[mt*8+nf];
          v_acc[mt*2+0] += __low2float(h0)*a4[0] + __high2float(h0)*a4[1];
          v_acc[mt*2+1] += __low2float(h1)*a4[2] + __high2float(h1)*a4[3];
        }
      }
      #pragma unroll
      for (int u=0;u<4;u++){
        float v = v_acc[u];
        v += __shfl_xor_sync(0xffffffffu, v, 1);
        v += __shfl_xor_sync(0xffffffffu, v, 2);
        if ((lane & 3) == 0){
          int row = wr*32 + (u>>1)*16 + (u&1)*8 + lane4;
          pvar[wc*128 + row] = v;
        }
      }
    }
    __syncthreads();

    if (tid < MM){
      size_t base = (size_t)ho*B_SZ + b0 + tid;
      out[base] = pmu[tid] + pmu[128+tid];
      out[(size_t)HOC*B_SZ + base] = sf2 - (pvar[tid] + pvar[128+tid]);
    }
    __syncthreads();
  }
}

// ---------------- launch ----------------
extern "C" void kernel_launch(void* const* d_in, const int* in_sizes, int n_in,
                              void* d_out, int out_size){
  const float* x      = (const float*)d_in[0];
  const float* z      = (const float*)d_in[1];
  const float* u_mean = (const float*)d_in[2];
  const float* u_tril = (const float*)d_in[3];
  const float* theta  = (const float*)d_in[4];
  float* out = (float*)d_out;

  cudaFuncSetAttribute(k_factor, cudaFuncAttributeMaxDynamicSharedMemorySize, N_TOT);
  cudaFuncSetAttribute(k_main,   cudaFuncAttributeMaxDynamicSharedMemorySize, SMEM_MAIN);

  k_prep<<<(NH*B_SZ + HOC*MM)/4, 256>>>(x, z, theta);
  k_factor<<<HOC, 256, N_TOT>>>(u_mean, u_tril);
  k_main<<<dim3(B_SZ/MM, HOC/G), 256, SMEM_MAIN>>>(out);
}

// round 12
// speedup vs baseline: 1.1990x; 1.1990x over previous
#include <cuda_runtime.h>
#include <cuda_bf16.h>
#include <math.h>
#include <cstdint>

#define B_SZ  4096
#define DIN   256
#define NOUT  32
#define MM    128
#define NH    2
#define HOC   (NH*NOUT)
#define JIT   1e-4f
#define TRILN (MM*(MM+1)/2)
#define D2CUT 170.0f

// ---------------- scratch ----------------
__device__ float g_sf2v[NH];
__device__ float g_x2[NH*B_SZ];
__device__ float g_z2[HOC*MM];
__device__ float g_cv[HOC*MM];
__device__ __align__(16) __nv_bfloat16 g_xb[NH*B_SZ*DIN];
__device__ __align__(16) __nv_bfloat16 g_zb[HOC*MM*DIN];
__device__ __align__(16) __nv_bfloat16 g_Qb[HOC*MM*MM];

// ---------------- helpers ----------------
__device__ __forceinline__ uint32_t smem_u32(const void* p){
  uint32_t a;
  asm("{ .reg .u64 t; cvta.to.shared.u64 t, %1; cvt.u32.u64 %0, t; }" : "=r"(a) : "l"(p));
  return a;
}
__device__ __forceinline__ void ldsm4(uint32_t addr, uint32_t* r){
  asm volatile("ldmatrix.sync.aligned.m8n8.x4.shared.b16 {%0,%1,%2,%3}, [%4];"
    : "=r"(r[0]),"=r"(r[1]),"=r"(r[2]),"=r"(r[3]) : "r"(addr));
}
__device__ __forceinline__ void mma16816(float* c, const uint32_t* a, const uint32_t* b){
  asm volatile("mma.sync.aligned.m16n8k16.row.col.f32.bf16.bf16.f32 "
    "{%0,%1,%2,%3}, {%4,%5,%6,%7}, {%8,%9}, {%0,%1,%2,%3};"
    : "+f"(c[0]),"+f"(c[1]),"+f"(c[2]),"+f"(c[3])
    : "r"(a[0]),"r"(a[1]),"r"(a[2]),"r"(a[3]), "r"(b[0]),"r"(b[1]));
}
#define CP16(dst, src) asm volatile("cp.async.cg.shared.global [%0], [%1], 16;" :: "r"(dst), "l"(src))
#define CP_COMMIT()    asm volatile("cp.async.commit_group;" ::: "memory")
#define CP_WAIT(n)     asm volatile("cp.async.wait_group %0;" :: "n"(n) : "memory")

__device__ __forceinline__ uint32_t pack_bf16x2(float lo, float hi){
  uint32_t r;
  asm("cvt.rn.satfinite.bf16x2.f32 %0, %1, %2;" : "=r"(r) : "f"(hi), "f"(lo));
  return r;
}
__device__ __forceinline__ float rbf(float sf2, float d2){
  return (d2 < D2CUT) ? sf2*__expf(-0.5f*d2) : 0.f;
}

#define SP2    80
#define XSTB   10240
#define KPITCH 272
#define XP     528
#define G      2

// 128x128x128 bf16 block GEMM from KPITCH tiles (k_factor use)
__device__ __forceinline__ void mm128(uint32_t aBase, uint32_t bBase,
                                      int wr, int wc, int l15, int lh,
                                      float acc[16][4]){
  uint32_t aB0 = aBase + (wr*32 + l15)*KPITCH + lh*16;
  uint32_t bB0 = bBase + (wc*64 + l15)*KPITCH + lh*16;
  #pragma unroll
  for (int ks=0;ks<8;ks++){
    uint32_t af[2][4], bt[4], bfr[8][2];
    #pragma unroll
    for (int mt=0;mt<2;mt++) ldsm4(aB0 + ks*32 + mt*16*KPITCH, af[mt]);
    #pragma unroll
    for (int nn=0;nn<4;nn++){
      ldsm4(bB0 + ks*32 + nn*16*KPITCH, bt);
      bfr[nn*2][0]=bt[0]; bfr[nn*2][1]=bt[2];
      bfr[nn*2+1][0]=bt[1]; bfr[nn*2+1][1]=bt[3];
    }
    #pragma unroll
    for (int mt=0;mt<2;mt++)
      #pragma unroll
      for (int nf=0;nf<8;nf++)
        mma16816(acc[mt*8+nf], af[mt], bfr[nf]);
  }
}

// one K=32 chunk, both operands SP2 pitch (k_factor)
__device__ __forceinline__ void chunk32(uint32_t aB, uint32_t bB, float acc[16][4]){
  #pragma unroll
  for (int ks=0;ks<2;ks++){
    uint32_t af[2][4], bt[4], bfr[8][2];
    #pragma unroll
    for (int mt=0;mt<2;mt++) ldsm4(aB + ks*32 + mt*16*SP2, af[mt]);
    #pragma unroll
    for (int nn=0;nn<4;nn++){
      ldsm4(bB + ks*32 + nn*16*SP2, bt);
      bfr[nn*2][0]=bt[0]; bfr[nn*2][1]=bt[2];
      bfr[nn*2+1][0]=bt[1]; bfr[nn*2+1][1]=bt[3];
    }
    #pragma unroll
    for (int mt=0;mt<2;mt++)
      #pragma unroll
      for (int nf=0;nf<8;nf++)
        mma16816(acc[mt*8+nf], af[mt], bfr[nf]);
  }
}

// one K=32 chunk: A from resident x (XP pitch), B from z ring (SP2 pitch)
__device__ __forceinline__ void chunk32x(uint32_t aB, uint32_t bB, float acc[16][4]){
  #pragma unroll
  for (int ks=0;ks<2;ks++){
    uint32_t af[2][4], bt[4], bfr[8][2];
    #pragma unroll
    for (int mt=0;mt<2;mt++) ldsm4(aB + ks*32 + mt*16*XP, af[mt]);
    #pragma unroll
    for (int nn=0;nn<4;nn++){
      ldsm4(bB + ks*32 + nn*16*SP2, bt);
      bfr[nn*2][0]=bt[0]; bfr[nn*2][1]=bt[2];
      bfr[nn*2+1][0]=bt[1]; bfr[nn*2+1][1]=bt[3];
    }
    #pragma unroll
    for (int mt=0;mt<2;mt++)
      #pragma unroll
      for (int nf=0;nf<8;nf++)
        mma16816(acc[mt*8+nf], af[mt], bfr[nf]);
  }
}

// ---------------- prep (unchanged, 8.2us) ----------------
__global__ void k_prep(const float* __restrict__ x, const float* __restrict__ z,
                       const float* __restrict__ theta){
  __shared__ float sscal[256];
  __shared__ float sw[8];
  int tid = threadIdx.x;
  int lane = tid & 31, wid = tid >> 5;
  int row0 = blockIdx.x*4;
  int hblk = (row0 < NH*B_SZ) ? (row0 / B_SZ)
                              : ((row0 - NH*B_SZ) / (NOUT*MM));
  sscal[tid] = expf(-theta[hblk*(DIN+1) + 1 + tid]);
  if (blockIdx.x == 0 && tid < NH) g_sf2v[tid] = expf(theta[tid*(DIN+1)]);
  __syncthreads();

  int rloc = tid >> 6;
  int col  = (tid & 63) << 2;
  int row  = row0 + rloc;

  const float* src; __nv_bfloat16* dst;
  if (row < NH*B_SZ){
    int b = row - hblk*B_SZ;
    src = x + (size_t)b*DIN;
    dst = g_xb + (size_t)row*DIN;
  } else {
    int id = row - NH*B_SZ;
    int om = id % (NOUT*MM);
    src = z + (size_t)om*DIN;
    dst = g_zb + (size_t)id*DIN;
  }
  float4 xv = *(const float4*)(src + col);
  float v0 = xv.x * sscal[col];
  float v1 = xv.y * sscal[col+1];
  float v2 = xv.z * sscal[col+2];
  float v3 = xv.w * sscal[col+3];
  uint2 pk = make_uint2(pack_bf16x2(v0,v1), pack_bf16x2(v2,v3));
  *(uint2*)(dst + col) = pk;

  float p = v0*v0 + v1*v1 + v2*v2 + v3*v3;
  #pragma unroll
  for (int o=16;o;o>>=1) p += __shfl_down_sync(0xffffffffu, p, o);
  if (lane == 0) sw[wid] = p;
  __syncthreads();
  if (tid < 4){
    float t = sw[2*tid] + sw[2*tid+1];
    int r = row0 + tid;
    if (r < NH*B_SZ) g_x2[r] = t; else g_z2[r - NH*B_SZ] = t;
  }
}

// ============ k_factor (unchanged from R10) ============
#define N_KB   0
#define N_XB   34816
#define N_YB   69632
#define N_UM   104448
#define N_PC   104960
#define N_TOT  105984

__global__ __launch_bounds__(256) void k_factor(const float* __restrict__ u_mean,
                                                const float* __restrict__ u_tril){
  extern __shared__ char smc[];
  uint32_t sb = smem_u32(smc);
  float* um = (float*)(smc + N_UM);
  float* pc = (float*)(smc + N_PC);

  int ho = blockIdx.x;
  int h = ho / NOUT, o = ho % NOUT;
  int tid = threadIdx.x;
  int wid = tid >> 5, lane = tid & 31;
  int wr = wid >> 1, wc = wid & 1;
  int l15 = lane & 15, lh = lane >> 4;
  int lane4 = lane >> 2, lpair = (lane & 3)*2;

  const __nv_bfloat16* zb = g_zb + (size_t)ho*MM*DIN;
  float sf2 = g_sf2v[h];
  float dK  = sf2 + JIT;
  float c0  = 1.0f / dK;

  if (tid < MM) um[tid] = u_mean[o*MM + tid];

  int offdiag_nz = 0;
  {
    uint32_t zs_base[3];
    #pragma unroll
    for (int s=0;s<3;s++) zs_base[s] = sb + N_YB + s*XSTB;
    int row0 = tid >> 2, q0 = tid & 3;
    int row1 = (tid+256) >> 2, q1 = (tid+256) & 3;
    #pragma unroll
    for (int s=0;s<2;s++){
      CP16(zs_base[s] + row0*SP2 + q0*16, zb + (size_t)row0*DIN + s*32 + q0*8);
      CP16(zs_base[s] + row1*SP2 + q1*16, zb + (size_t)row1*DIN + s*32 + q1*8);
      CP_COMMIT();
    }

    float acc[16][4];
    #pragma unroll
    for (int i=0;i<16;i++)
      #pragma unroll
      for (int j=0;j<4;j++) acc[i][j]=0.f;

    uint32_t aoff = (wr*32 + l15)*SP2 + lh*16;
    uint32_t boff = (wc*64 + l15)*SP2 + lh*16;
    #pragma unroll 1
    for (int c=0;c<8;c++){
      if (c == 7) { CP_WAIT(0); } else { CP_WAIT(1); }
      __syncthreads();
      int cur = c % 3;
      chunk32(zs_base[cur] + aoff, zs_base[cur] + boff, acc);
      if (c < 6){
        int nx = (c+2)%3;
        CP16(zs_base[nx] + row0*SP2 + q0*16, zb + (size_t)row0*DIN + (c+2)*32 + q0*8);
        CP16(zs_base[nx] + row1*SP2 + q1*16, zb + (size_t)row1*DIN + (c+2)*32 + q1*8);
        CP_COMMIT();
      }
    }

    #pragma unroll
    for (int mt=0;mt<2;mt++){
      int r0 = wr*32 + mt*16 + lane4;
      int r1 = r0 + 8;
      float z20 = g_z2[ho*MM+r0], z21 = g_z2[ho*MM+r1];
      #pragma unroll
      for (int nf=0;nf<8;nf++){
        int cb = wc*64 + nf*8 + lpair;
        float zc0 = g_z2[ho*MM+cb], zc1 = g_z2[ho*MM+cb+1];
        float* a4 = acc[mt*8+nf];
        float v00 = (r0==cb  ) ? dK : rbf(sf2, fmaxf(z20+zc0-2.f*a4[0],0.f));
        float v01 = (r0==cb+1) ? dK : rbf(sf2, fmaxf(z20+zc1-2.f*a4[1],0.f));
        float v10 = (r1==cb  ) ? dK : rbf(sf2, fmaxf(z21+zc0-2.f*a4[2],0.f));
        float v11 = (r1==cb+1) ? dK : rbf(sf2, fmaxf(z21+zc1-2.f*a4[3],0.f));
        if ((r0!=cb   && v00!=0.f) || (r0!=cb+1 && v01!=0.f) ||
            (r1!=cb   && v10!=0.f) || (r1!=cb+1 && v11!=0.f)) offdiag_nz = 1;
        *(uint32_t*)(smc + N_KB + r0*KPITCH + cb*2) = pack_bf16x2(v00,v01);
        *(uint32_t*)(smc + N_KB + r1*KPITCH + cb*2) = pack_bf16x2(v10,v11);
        float x00 = (r0==cb  ) ? c0 : 0.f;
        float x01 = (r0==cb+1) ? c0 : 0.f;
        float x10 = (r1==cb  ) ? c0 : 0.f;
        float x11 = (r1==cb+1) ? c0 : 0.f;
        *(uint32_t*)(smc + N_XB + r0*KPITCH + cb*2) = pack_bf16x2(x00,x01);
        *(uint32_t*)(smc + N_XB + r1*KPITCH + cb*2) = pack_bf16x2(x10,x11);
      }
    }
  }

  int any = __syncthreads_or(offdiag_nz);

  if (!any){
    if (tid < MM) g_cv[ho*MM + tid] = c0 * um[tid];
    {
      const float* Lv = u_tril + (size_t)o*TRILN;
      for (int it=0; it<32; it++){
        int idx = tid + it*256;
        int j = idx & 127, kp = (idx >> 7)*2;
        float v0 = (kp   >= j) ? c0*Lv[(kp*(kp+1))/2 + j] : 0.f;
        float v1 = (kp+1 >= j) ? c0*Lv[((kp+1)*(kp+2))/2 + j] : 0.f;
        *(uint32_t*)(smc + N_KB + j*KPITCH + kp*2) = pack_bf16x2(v0, v1);
      }
    }
    __syncthreads();
    float acc[16][4];
    #pragma unroll
    for (int i=0;i<16;i++)
      #pragma unroll
      for (int j=0;j<4;j++) acc[i][j]=0.f;
    mm128(sb + N_KB, sb + N_KB, wr, wc, l15, lh, acc);
    __nv_bfloat16* Qg = g_Qb + (size_t)ho*MM*MM;
    #pragma unroll
    for (int mt=0;mt<2;mt++){
      int r0 = wr*32 + mt*16 + lane4;
      int r1 = r0 + 8;
      #pragma unroll
      for (int nf=0;nf<8;nf++){
        int cb = wc*64 + nf*8 + lpair;
        float* a4 = acc[mt*8+nf];
        float q00 = ((r0==cb  ) ? c0 : 0.f) - a4[0];
        float q01 = ((r0==cb+1) ? c0 : 0.f) - a4[1];
        float q10 = ((r1==cb  ) ? c0 : 0.f) - a4[2];
        float q11 = ((r1==cb+1) ? c0 : 0.f) - a4[3];
        *(uint32_t*)&Qg[(size_t)r0*MM + cb] = pack_bf16x2(q00,q01);
        *(uint32_t*)&Qg[(size_t)r1*MM + cb] = pack_bf16x2(q10,q11);
      }
    }
    return;
  }

  // slow path: Newton-Schulz x2
  #pragma unroll 1
  for (int it=0; it<2; it++){
    __syncthreads();
    {
      float acc[16][4];
      #pragma unroll
      for (int i=0;i<16;i++)
        #pragma unroll
        for (int j=0;j<4;j++) acc[i][j]=0.f;
      mm128(sb + N_KB, sb + N_XB, wr, wc, l15, lh, acc);
      #pragma unroll
      for (int mt=0;mt<2;mt++){
        int r0 = wr*32 + mt*16 + lane4;
        int r1 = r0 + 8;
        #pragma unroll
        for (int nf=0;nf<8;nf++){
          int cb = wc*64 + nf*8 + lpair;
          float* a4 = acc[mt*8+nf];
          *(uint32_t*)(smc + N_YB + r0*KPITCH + cb*2) = pack_bf16x2(a4[0],a4[1]);
          *(uint32_t*)(smc + N_YB + r1*KPITCH + cb*2) = pack_bf16x2(a4[2],a4[3]);
        }
      }
    }
    __syncthreads();
    {
      float acc[16][4];
      #pragma unroll
      for (int i=0;i<16;i++)
        #pragma unroll
        for (int j=0;j<4;j++) acc[i][j]=0.f;
      mm128(sb + N_XB, sb + N_YB, wr, wc, l15, lh, acc);
      __syncthreads();
      float c_acc[4] = {0.f,0.f,0.f,0.f};
      #pragma unroll
      for (int mt=0;mt<2;mt++){
        int r0 = wr*32 + mt*16 + lane4;
        int r1 = r0 + 8;
        #pragma unroll
        for (int nf=0;nf<8;nf++){
          int cb = wc*64 + nf*8 + lpair;
          uint32_t p0 = *(const uint32_t*)(smc + N_XB + r0*KPITCH + cb*2);
          uint32_t p1 = *(const uint32_t*)(smc + N_XB + r1*KPITCH + cb*2);
          __nv_bfloat162 h0 = *reinterpret_cast<__nv_bfloat162*>(&p0);
          __nv_bfloat162 h1 = *reinterpret_cast<__nv_bfloat162*>(&p1);
          float* a4 = acc[mt*8+nf];
          float n00 = 2.f*__low2float(h0)  - a4[0];
          float n01 = 2.f*__high2float(h0) - a4[1];
          float n10 = 2.f*__low2float(h1)  - a4[2];
          float n11 = 2.f*__high2float(h1) - a4[3];
          *(uint32_t*)(smc + N_XB + r0*KPITCH + cb*2) = pack_bf16x2(n00,n01);
          *(uint32_t*)(smc + N_XB + r1*KPITCH + cb*2) = pack_bf16x2(n10,n11);
          if (it == 1){
            float u0 = um[cb], u1 = um[cb+1];
            c_acc[mt*2+0] += n00*u0 + n01*u1;
            c_acc[mt*2+1] += n10*u0 + n11*u1;
          }
        }
      }
      if (it == 1){
        #pragma unroll
        for (int u=0;u<4;u++){
          float v = c_acc[u];
          v += __shfl_xor_sync(0xffffffffu, v, 1);
          v += __shfl_xor_sync(0xffffffffu, v, 2);
          if ((lane & 3) == 0){
            int row = wr*32 + (u>>1)*16 + (u&1)*8 + lane4;
            pc[wc*128 + row] = v;
          }
        }
      }
    }
  }
  __syncthreads();
  if (tid < MM) g_cv[ho*MM + tid] = pc[tid] + pc[128+tid];

  {
    const float* Lv = u_tril + (size_t)o*TRILN;
    for (int it=0; it<32; it++){
      int idx = tid + it*256;
      int j = idx & 127, kp = (idx >> 7)*2;
      float v0 = (kp   >= j) ? Lv[(kp*(kp+1))/2 + j] : 0.f;
      float v1 = (kp+1 >= j) ? Lv[((kp+1)*(kp+2))/2 + j] : 0.f;
      *(uint32_t*)(smc + N_KB + j*KPITCH + kp*2) = pack_bf16x2(v0, v1);
    }
  }
  __syncthreads();

  {
    float acc[16][4];
    #pragma unroll
    for (int i=0;i<16;i++)
      #pragma unroll
      for (int j=0;j<4;j++) acc[i][j]=0.f;
    mm128(sb + N_XB, sb + N_KB, wr, wc, l15, lh, acc);
    __syncthreads();
    #pragma unroll
    for (int mt=0;mt<2;mt++){
      int r0 = wr*32 + mt*16 + lane4;
      int r1 = r0 + 8;
      #pragma unroll
      for (int nf=0;nf<8;nf++){
        int cb = wc*64 + nf*8 + lpair;
        float* a4 = acc[mt*8+nf];
        *(uint32_t*)(smc + N_YB + r0*KPITCH + cb*2) = pack_bf16x2(a4[0],a4[1]);
        *(uint32_t*)(smc + N_YB + r1*KPITCH + cb*2) = pack_bf16x2(a4[2],a4[3]);
      }
    }
  }
  __syncthreads();

  {
    float acc[16][4];
    #pragma unroll
    for (int i=0;i<16;i++)
      #pragma unroll
      for (int j=0;j<4;j++) acc[i][j]=0.f;
    mm128(sb + N_YB, sb + N_YB, wr, wc, l15, lh, acc);
    __nv_bfloat16* Qg = g_Qb + (size_t)ho*MM*MM;
    #pragma unroll
    for (int mt=0;mt<2;mt++){
      int r0 = wr*32 + mt*16 + lane4;
      int r1 = r0 + 8;
      #pragma unroll
      for (int nf=0;nf<8;nf++){
        int cb = wc*64 + nf*8 + lpair;
        uint32_t p0 = *(const uint32_t*)(smc + N_XB + r0*KPITCH + cb*2);
        uint32_t p1 = *(const uint32_t*)(smc + N_XB + r1*KPITCH + cb*2);
        __nv_bfloat162 h0 = *reinterpret_cast<__nv_bfloat162*>(&p0);
        __nv_bfloat162 h1 = *reinterpret_cast<__nv_bfloat162*>(&p1);
        float* a4 = acc[mt*8+nf];
        *(uint32_t*)&Qg[(size_t)r0*MM + cb] = pack_bf16x2(__low2float(h0)-a4[0], __high2float(h0)-a4[1]);
        *(uint32_t*)&Qg[(size_t)r1*MM + cb] = pack_bf16x2(__low2float(h1)-a4[2], __high2float(h1)-a4[3]);
      }
    }
  }
}

// ============ k_main: resident x, G=2, 2 CTA/SM; rare path = scalar fallback ============
#define OFF_X2   0        // 512
#define OFF_Z2   512      // 512
#define OFF_RED  1024     // 1024 (rare-path var partials, 256 f32)
#define OFF_MU   2048     // 512  (rare-path mu, 128 f32)
#define OFF_XR   3584     // 128*528 = 67584 -> 71168 (also rare-path kuf tile, KPITCH)
#define OFF_ZR   71168    // 3*10240 -> 101888
#define SMEM_MAIN 101888

__global__ __launch_bounds__(256,2) void k_main(float* __restrict__ out){
  extern __shared__ char smc[];
  uint32_t sb = smem_u32(smc);
  float* sx2 = (float*)(smc + OFF_X2);
  float* sz2 = (float*)(smc + OFF_Z2);
  float* red = (float*)(smc + OFF_RED);
  float* muv = (float*)(smc + OFF_MU);

  int ho0 = blockIdx.y * G;
  int h   = ho0 / NOUT;
  int b0  = blockIdx.x * MM;
  int tid = threadIdx.x;
  int wid = tid >> 5, lane = tid & 31;
  int wr = wid >> 1, wc = wid & 1;
  int l15 = lane & 15, lh = lane >> 4;
  int lane4 = lane >> 2, lpair = (lane & 3)*2;

  if (tid < MM) sx2[tid] = g_x2[h*B_SZ + b0 + tid];

  const __nv_bfloat16* xb = g_xb + ((size_t)h*B_SZ + b0)*DIN;
  float sf2 = g_sf2v[h];

  uint32_t zr_base[3];
  #pragma unroll
  for (int s=0;s<3;s++) zr_base[s] = sb + OFF_ZR + s*XSTB;
  int zr0 = tid >> 2, zq0 = tid & 3;
  int zr1 = (tid+256) >> 2, zq1 = (tid+256) & 3;

  // stage resident x + z chunks 0,1
  {
    #pragma unroll
    for (int it=0; it<16; it++){
      int seg = tid + it*256;
      int r = seg >> 5, q = seg & 31;
      CP16(sb + OFF_XR + r*XP + q*16, xb + (size_t)r*DIN + q*8);
    }
    const __nv_bfloat16* zb0 = g_zb + (size_t)ho0*MM*DIN;
    CP16(zr_base[0] + zr0*SP2 + zq0*16, zb0 + (size_t)zr0*DIN + 0 + zq0*8);
    CP16(zr_base[0] + zr1*SP2 + zq1*16, zb0 + (size_t)zr1*DIN + 0 + zq1*8);
    CP_COMMIT();
    CP16(zr_base[1] + zr0*SP2 + zq0*16, zb0 + (size_t)zr0*DIN + 32 + zq0*8);
    CP16(zr_base[1] + zr1*SP2 + zq1*16, zb0 + (size_t)zr1*DIN + 32 + zq1*8);
    CP_COMMIT();
  }

  uint32_t aoffA = (wr*32 + l15)*XP + lh*16;
  uint32_t boffA = (wc*64 + l15)*SP2 + lh*16;

  #pragma unroll 1
  for (int g=0; g<G; g++){
    int ho = ho0 + g;
    if (tid < MM) sz2[tid] = g_z2[ho*MM + tid];

    float acc[16][4];
    #pragma unroll
    for (int i=0;i<16;i++)
      #pragma unroll
      for (int j=0;j<4;j++) acc[i][j]=0.f;

    #pragma unroll 1
    for (int c=0;c<8;c++){
      int t = g*8 + c;
      CP_WAIT(1);
      __syncthreads();
      chunk32x(sb + OFF_XR + aoffA + c*64, zr_base[t%3] + boffA, acc);
      int tn = t + 2;
      if (tn < G*8){
        const __nv_bfloat16* zbn = g_zb + (size_t)(ho0 + (tn>>3))*MM*DIN;
        int cn = tn & 7;
        CP16(zr_base[tn%3] + zr0*SP2 + zq0*16, zbn + (size_t)zr0*DIN + cn*32 + zq0*8);
        CP16(zr_base[tn%3] + zr1*SP2 + zq1*16, zbn + (size_t)zr1*DIN + cn*32 + zq1*8);
      }
      CP_COMMIT();   // uniform one group per iteration
    }

    // epilogue: kuf in registers + zero vote
    uint32_t nzbits = 0;
    #pragma unroll
    for (int mt=0;mt<2;mt++){
      int r0 = wr*32 + mt*16 + lane4;
      int r1 = r0 + 8;
      float x20 = sx2[r0], x21 = sx2[r1];
      #pragma unroll
      for (int nf=0;nf<8;nf++){
        int cb = wc*64 + nf*8 + lpair;
        float z20 = sz2[cb], z21 = sz2[cb+1];
        float* a4 = acc[mt*8+nf];
        a4[0] = rbf(sf2, fmaxf(x20 + z20 - 2.f*a4[0], 0.f));
        a4[1] = rbf(sf2, fmaxf(x20 + z21 - 2.f*a4[1], 0.f));
        a4[2] = rbf(sf2, fmaxf(x21 + z20 - 2.f*a4[2], 0.f));
        a4[3] = rbf(sf2, fmaxf(x21 + z21 - 2.f*a4[3], 0.f));
        nzbits |= __float_as_uint(a4[0]) | __float_as_uint(a4[1]) |
                  __float_as_uint(a4[2]) | __float_as_uint(a4[3]);
      }
    }

    int any = __syncthreads_or((int)nzbits);

    if (!any){
      // kuf == 0 exactly: mu = 0, var = sf2
      if (tid < MM){
        size_t base = (size_t)ho*B_SZ + b0 + tid;
        out[base] = 0.f;
        out[(size_t)HOC*B_SZ + base] = sf2;
      }
      continue;
    }

    // ================= RARE path (correct, slow; clobbers resident x) =================
    // drain pending z prefetches into smem before clobbering anything
    CP_WAIT(0);
    __syncthreads();
    // write kuf bf16 tile into XR region (KPITCH layout)
    #pragma unroll
    for (int mt=0;mt<2;mt++){
      int r0 = wr*32 + mt*16 + lane4;
      int r1 = r0 + 8;
      #pragma unroll
      for (int nf=0;nf<8;nf++){
        int cb = wc*64 + nf*8 + lpair;
        float* a4 = acc[mt*8+nf];
        *(uint32_t*)(smc + OFF_XR + r0*KPITCH + cb*2) = pack_bf16x2(a4[0],a4[1]);
        *(uint32_t*)(smc + OFF_XR + r1*KPITCH + cb*2) = pack_bf16x2(a4[2],a4[3]);
      }
    }
    __syncthreads();
    // scalar fallback: 2 threads per row (j-halves); thread with half==0 also does mu
    {
      int r = tid >> 1, halfsel = tid & 1;
      const __nv_bfloat16* Qg = g_Qb + (size_t)ho*MM*MM;
      const float* cv = g_cv + ho*MM;
      const __nv_bfloat16* krow = (const __nv_bfloat16*)(smc + OFF_XR + r*KPITCH);
      float var_p = 0.f;
      for (int j = halfsel*64; j < halfsel*64+64; j++){
        float y = 0.f;
        const __nv_bfloat16* qrow = Qg + (size_t)j*MM;
        for (int m=0;m<MM;m++)
          y += __bfloat162float(krow[m]) * __bfloat162float(qrow[m]);
        var_p += y * __bfloat162float(krow[j]);
      }
      red[tid] = var_p;
      if (halfsel == 0){
        float mu = 0.f;
        for (int m=0;m<MM;m++) mu += cv[m]*__bfloat162float(krow[m]);
        muv[r] = mu;
      }
    }
    __syncthreads();
    if (tid < MM){
      size_t base = (size_t)ho*B_SZ + b0 + tid;
      out[base] = muv[tid];
      out[(size_t)HOC*B_SZ + base] = sf2 - (red[2*tid] + red[2*tid+1]);
    }
    __syncthreads();
    // re-stage resident x if more groups remain (z ring contents already staged & drained)
    if (g+1 < G){
      #pragma unroll
      for (int it=0; it<16; it++){
        int seg = tid + it*256;
        int rr = seg >> 5, q = seg & 31;
        CP16(sb + OFF_XR + rr*XP + q*16, xb + (size_t)rr*DIN + q*8);
      }
      CP_COMMIT();
      CP_WAIT(0);
      __syncthreads();
    }
  }
}

// ---------------- launch ----------------
extern "C" void kernel_launch(void* const* d_in, const int* in_sizes, int n_in,
                              void* d_out, int out_size){
  const float* x      = (const float*)d_in[0];
  const float* z      = (const float*)d_in[1];
  const float* u_mean = (const float*)d_in[2];
  const float* u_tril = (const float*)d_in[3];
  const float* theta  = (const float*)d_in[4];
  float* out = (float*)d_out;

  cudaFuncSetAttribute(k_factor, cudaFuncAttributeMaxDynamicSharedMemorySize, N_TOT);
  cudaFuncSetAttribute(k_main,   cudaFuncAttributeMaxDynamicSharedMemorySize, SMEM_MAIN);

  k_prep<<<(NH*B_SZ + HOC*MM)/4, 256>>>(x, z, theta);
  k_factor<<<HOC, 256, N_TOT>>>(u_mean, u_tril);
  k_main<<<dim3(B_SZ/MM, HOC/G), 256, SMEM_MAIN>>>(out);
}

// round 13
// speedup vs baseline: 1.3654x; 1.1388x over previous
#include <cuda_runtime.h>
#include <cuda_bf16.h>
#include <math.h>
#include <cstdint>

#define B_SZ  4096
#define DIN   256
#define NOUT  32
#define MM    128
#define NH    2
#define HOC   (NH*NOUT)
#define JIT   1e-4f
#define TRILN (MM*(MM+1)/2)
#define D2CUT 170.0f

// ---------------- scratch ----------------
__device__ float g_sf2v[NH];
__device__ float g_x2[NH*B_SZ];
__device__ float g_z2[HOC*MM];
__device__ float g_cv[HOC*MM];
__device__ __align__(16) __nv_bfloat16 g_xb[NH*B_SZ*DIN];
__device__ __align__(16) __nv_bfloat16 g_zb[HOC*MM*DIN];
__device__ __align__(16) __nv_bfloat16 g_Qb[HOC*MM*MM];

// ---------------- helpers ----------------
__device__ __forceinline__ uint32_t smem_u32(const void* p){
  uint32_t a;
  asm("{ .reg .u64 t; cvta.to.shared.u64 t, %1; cvt.u32.u64 %0, t; }" : "=r"(a) : "l"(p));
  return a;
}
__device__ __forceinline__ void ldsm4(uint32_t addr, uint32_t* r){
  asm volatile("ldmatrix.sync.aligned.m8n8.x4.shared.b16 {%0,%1,%2,%3}, [%4];"
    : "=r"(r[0]),"=r"(r[1]),"=r"(r[2]),"=r"(r[3]) : "r"(addr));
}
__device__ __forceinline__ void mma16816(float* c, const uint32_t* a, const uint32_t* b){
  asm volatile("mma.sync.aligned.m16n8k16.row.col.f32.bf16.bf16.f32 "
    "{%0,%1,%2,%3}, {%4,%5,%6,%7}, {%8,%9}, {%0,%1,%2,%3};"
    : "+f"(c[0]),"+f"(c[1]),"+f"(c[2]),"+f"(c[3])
    : "r"(a[0]),"r"(a[1]),"r"(a[2]),"r"(a[3]), "r"(b[0]),"r"(b[1]));
}
#define CP16(dst, src) asm volatile("cp.async.cg.shared.global [%0], [%1], 16;" :: "r"(dst), "l"(src))
#define CP_COMMIT()    asm volatile("cp.async.commit_group;" ::: "memory")
#define CP_WAIT(n)     asm volatile("cp.async.wait_group %0;" :: "n"(n) : "memory")

__device__ __forceinline__ uint32_t pack_bf16x2(float lo, float hi){
  uint32_t r;
  asm("cvt.rn.satfinite.bf16x2.f32 %0, %1, %2;" : "=r"(r) : "f"(hi), "f"(lo));
  return r;
}
__device__ __forceinline__ float rbf(float sf2, float d2){
  return (d2 < D2CUT) ? sf2*__expf(-0.5f*d2) : 0.f;
}

#define SP2    80
#define XSTB   10240
#define KPITCH 272
#define XP     528
#define G      2

// 128x128x128 bf16 block GEMM from KPITCH tiles (k_factor use)
__device__ __forceinline__ void mm128(uint32_t aBase, uint32_t bBase,
                                      int wr, int wc, int l15, int lh,
                                      float acc[16][4]){
  uint32_t aB0 = aBase + (wr*32 + l15)*KPITCH + lh*16;
  uint32_t bB0 = bBase + (wc*64 + l15)*KPITCH + lh*16;
  #pragma unroll
  for (int ks=0;ks<8;ks++){
    uint32_t af[2][4], bt[4], bfr[8][2];
    #pragma unroll
    for (int mt=0;mt<2;mt++) ldsm4(aB0 + ks*32 + mt*16*KPITCH, af[mt]);
    #pragma unroll
    for (int nn=0;nn<4;nn++){
      ldsm4(bB0 + ks*32 + nn*16*KPITCH, bt);
      bfr[nn*2][0]=bt[0]; bfr[nn*2][1]=bt[2];
      bfr[nn*2+1][0]=bt[1]; bfr[nn*2+1][1]=bt[3];
    }
    #pragma unroll
    for (int mt=0;mt<2;mt++)
      #pragma unroll
      for (int nf=0;nf<8;nf++)
        mma16816(acc[mt*8+nf], af[mt], bfr[nf]);
  }
}

__device__ __forceinline__ void chunk32(uint32_t aB, uint32_t bB, float acc[16][4]){
  #pragma unroll
  for (int ks=0;ks<2;ks++){
    uint32_t af[2][4], bt[4], bfr[8][2];
    #pragma unroll
    for (int mt=0;mt<2;mt++) ldsm4(aB + ks*32 + mt*16*SP2, af[mt]);
    #pragma unroll
    for (int nn=0;nn<4;nn++){
      ldsm4(bB + ks*32 + nn*16*SP2, bt);
      bfr[nn*2][0]=bt[0]; bfr[nn*2][1]=bt[2];
      bfr[nn*2+1][0]=bt[1]; bfr[nn*2+1][1]=bt[3];
    }
    #pragma unroll
    for (int mt=0;mt<2;mt++)
      #pragma unroll
      for (int nf=0;nf<8;nf++)
        mma16816(acc[mt*8+nf], af[mt], bfr[nf]);
  }
}

__device__ __forceinline__ void chunk32x(uint32_t aB, uint32_t bB, float acc[16][4]){
  #pragma unroll
  for (int ks=0;ks<2;ks++){
    uint32_t af[2][4], bt[4], bfr[8][2];
    #pragma unroll
    for (int mt=0;mt<2;mt++) ldsm4(aB + ks*32 + mt*16*XP, af[mt]);
    #pragma unroll
    for (int nn=0;nn<4;nn++){
      ldsm4(bB + ks*32 + nn*16*SP2, bt);
      bfr[nn*2][0]=bt[0]; bfr[nn*2][1]=bt[2];
      bfr[nn*2+1][0]=bt[1]; bfr[nn*2+1][1]=bt[3];
    }
    #pragma unroll
    for (int mt=0;mt<2;mt++)
      #pragma unroll
      for (int nf=0;nf<8;nf++)
        mma16816(acc[mt*8+nf], af[mt], bfr[nf]);
  }
}

// ---------------- prep (unchanged) ----------------
__global__ void k_prep(const float* __restrict__ x, const float* __restrict__ z,
                       const float* __restrict__ theta){
  __shared__ float sscal[256];
  __shared__ float sw[8];
  int tid = threadIdx.x;
  int lane = tid & 31, wid = tid >> 5;
  int row0 = blockIdx.x*4;
  int hblk = (row0 < NH*B_SZ) ? (row0 / B_SZ)
                              : ((row0 - NH*B_SZ) / (NOUT*MM));
  sscal[tid] = expf(-theta[hblk*(DIN+1) + 1 + tid]);
  if (blockIdx.x == 0 && tid < NH) g_sf2v[tid] = expf(theta[tid*(DIN+1)]);
  __syncthreads();

  int rloc = tid >> 6;
  int col  = (tid & 63) << 2;
  int row  = row0 + rloc;

  const float* src; __nv_bfloat16* dst;
  if (row < NH*B_SZ){
    int b = row - hblk*B_SZ;
    src = x + (size_t)b*DIN;
    dst = g_xb + (size_t)row*DIN;
  } else {
    int id = row - NH*B_SZ;
    int om = id % (NOUT*MM);
    src = z + (size_t)om*DIN;
    dst = g_zb + (size_t)id*DIN;
  }
  float4 xv = *(const float4*)(src + col);
  float v0 = xv.x * sscal[col];
  float v1 = xv.y * sscal[col+1];
  float v2 = xv.z * sscal[col+2];
  float v3 = xv.w * sscal[col+3];
  uint2 pk = make_uint2(pack_bf16x2(v0,v1), pack_bf16x2(v2,v3));
  *(uint2*)(dst + col) = pk;

  float p = v0*v0 + v1*v1 + v2*v2 + v3*v3;
  #pragma unroll
  for (int o=16;o;o>>=1) p += __shfl_down_sync(0xffffffffu, p, o);
  if (lane == 0) sw[wid] = p;
  __syncthreads();
  if (tid < 4){
    float t = sw[2*tid] + sw[2*tid+1];
    int r = row0 + tid;
    if (r < NH*B_SZ) g_x2[r] = t; else g_z2[r - NH*B_SZ] = t;
  }
}

// ============ k_factor: 4-stage ring + exp-skip epilogue ============
#define N_KB   0
#define N_XB   34816
#define N_YB   69632
#define N_UM   104448
#define N_PC   104960
#define N_TOT  105984

__global__ __launch_bounds__(256) void k_factor(const float* __restrict__ u_mean,
                                                const float* __restrict__ u_tril){
  extern __shared__ char smc[];
  uint32_t sb = smem_u32(smc);
  float* um = (float*)(smc + N_UM);
  float* pc = (float*)(smc + N_PC);

  int ho = blockIdx.x;
  int h = ho / NOUT, o = ho % NOUT;
  int tid = threadIdx.x;
  int wid = tid >> 5, lane = tid & 31;
  int wr = wid >> 1, wc = wid & 1;
  int l15 = lane & 15, lh = lane >> 4;
  int lane4 = lane >> 2, lpair = (lane & 3)*2;

  const __nv_bfloat16* zb = g_zb + (size_t)ho*MM*DIN;
  float sf2 = g_sf2v[h];
  float dK  = sf2 + JIT;
  float c0  = 1.0f / dK;

  if (tid < MM) um[tid] = u_mean[o*MM + tid];

  int offdiag_nz = 0;
  {
    uint32_t zs_base[4] = { sb + N_YB, sb + N_YB + XSTB, sb + N_YB + 2*XSTB,
                            sb + N_XB };   // 4th stage borrows Xb (dead until epilogue)
    int row0 = tid >> 2, q0 = tid & 3;
    int row1 = (tid+256) >> 2, q1 = (tid+256) & 3;
    #pragma unroll
    for (int s=0;s<3;s++){
      CP16(zs_base[s] + row0*SP2 + q0*16, zb + (size_t)row0*DIN + s*32 + q0*8);
      CP16(zs_base[s] + row1*SP2 + q1*16, zb + (size_t)row1*DIN + s*32 + q1*8);
      CP_COMMIT();
    }

    float acc[16][4];
    #pragma unroll
    for (int i=0;i<16;i++)
      #pragma unroll
      for (int j=0;j<4;j++) acc[i][j]=0.f;

    uint32_t aoff = (wr*32 + l15)*SP2 + lh*16;
    uint32_t boff = (wc*64 + l15)*SP2 + lh*16;
    #pragma unroll 1
    for (int c=0;c<8;c++){
      CP_WAIT(2);
      __syncthreads();
      chunk32(zs_base[c%4] + aoff, zs_base[c%4] + boff, acc);
      if (c < 5){
        int nx = (c+3)%4;
        CP16(zs_base[nx] + row0*SP2 + q0*16, zb + (size_t)row0*DIN + (c+3)*32 + q0*8);
        CP16(zs_base[nx] + row1*SP2 + q1*16, zb + (size_t)row1*DIN + (c+3)*32 + q1*8);
      }
      CP_COMMIT();
    }
    CP_WAIT(0);
    __syncthreads();   // stage region (incl. Xb) fully drained before epilogue writes

    // epilogue: d2 pass + warp exp-skip vote
    float locmin = 1e30f;
    #pragma unroll
    for (int mt=0;mt<2;mt++){
      int r0 = wr*32 + mt*16 + lane4;
      int r1 = r0 + 8;
      float z20 = g_z2[ho*MM+r0], z21 = g_z2[ho*MM+r1];
      #pragma unroll
      for (int nf=0;nf<8;nf++){
        int cb = wc*64 + nf*8 + lpair;
        float zc0 = g_z2[ho*MM+cb], zc1 = g_z2[ho*MM+cb+1];
        float* a4 = acc[mt*8+nf];
        a4[0] = fmaxf(z20+zc0-2.f*a4[0], 0.f);
        a4[1] = fmaxf(z20+zc1-2.f*a4[1], 0.f);
        a4[2] = fmaxf(z21+zc0-2.f*a4[2], 0.f);
        a4[3] = fmaxf(z21+zc1-2.f*a4[3], 0.f);
        locmin = fminf(locmin, fminf(fminf(a4[0],a4[1]), fminf(a4[2],a4[3])));
      }
    }
    int allbig = __all_sync(0xffffffffu, locmin >= D2CUT);
    #pragma unroll
    for (int mt=0;mt<2;mt++){
      int r0 = wr*32 + mt*16 + lane4;
      int r1 = r0 + 8;
      #pragma unroll
      for (int nf=0;nf<8;nf++){
        int cb = wc*64 + nf*8 + lpair;
        float* a4 = acc[mt*8+nf];
        float v00, v01, v10, v11;
        if (allbig){
          v00 = v01 = v10 = v11 = 0.f;   // no diag inside an allbig warp (diag d2=0)
        } else {
          v00 = (r0==cb  ) ? dK : rbf(sf2, a4[0]);
          v01 = (r0==cb+1) ? dK : rbf(sf2, a4[1]);
          v10 = (r1==cb  ) ? dK : rbf(sf2, a4[2]);
          v11 = (r1==cb+1) ? dK : rbf(sf2, a4[3]);
          if ((r0!=cb   && v00!=0.f) || (r0!=cb+1 && v01!=0.f) ||
              (r1!=cb   && v10!=0.f) || (r1!=cb+1 && v11!=0.f)) offdiag_nz = 1;
        }
        *(uint32_t*)(smc + N_KB + r0*KPITCH + cb*2) = pack_bf16x2(v00,v01);
        *(uint32_t*)(smc + N_KB + r1*KPITCH + cb*2) = pack_bf16x2(v10,v11);
        float x00 = (r0==cb  ) ? c0 : 0.f;
        float x01 = (r0==cb+1) ? c0 : 0.f;
        float x10 = (r1==cb  ) ? c0 : 0.f;
        float x11 = (r1==cb+1) ? c0 : 0.f;
        *(uint32_t*)(smc + N_XB + r0*KPITCH + cb*2) = pack_bf16x2(x00,x01);
        *(uint32_t*)(smc + N_XB + r1*KPITCH + cb*2) = pack_bf16x2(x10,x11);
      }
    }
  }

  int any = __syncthreads_or(offdiag_nz);

  if (!any){
    if (tid < MM) g_cv[ho*MM + tid] = c0 * um[tid];
    {
      const float* Lv = u_tril + (size_t)o*TRILN;
      for (int it=0; it<32; it++){
        int idx = tid + it*256;
        int j = idx & 127, kp = (idx >> 7)*2;
        float v0 = (kp   >= j) ? c0*Lv[(kp*(kp+1))/2 + j] : 0.f;
        float v1 = (kp+1 >= j) ? c0*Lv[((kp+1)*(kp+2))/2 + j] : 0.f;
        *(uint32_t*)(smc + N_KB + j*KPITCH + kp*2) = pack_bf16x2(v0, v1);
      }
    }
    __syncthreads();
    float acc[16][4];
    #pragma unroll
    for (int i=0;i<16;i++)
      #pragma unroll
      for (int j=0;j<4;j++) acc[i][j]=0.f;
    mm128(sb + N_KB, sb + N_KB, wr, wc, l15, lh, acc);
    __nv_bfloat16* Qg = g_Qb + (size_t)ho*MM*MM;
    #pragma unroll
    for (int mt=0;mt<2;mt++){
      int r0 = wr*32 + mt*16 + lane4;
      int r1 = r0 + 8;
      #pragma unroll
      for (int nf=0;nf<8;nf++){
        int cb = wc*64 + nf*8 + lpair;
        float* a4 = acc[mt*8+nf];
        float q00 = ((r0==cb  ) ? c0 : 0.f) - a4[0];
        float q01 = ((r0==cb+1) ? c0 : 0.f) - a4[1];
        float q10 = ((r1==cb  ) ? c0 : 0.f) - a4[2];
        float q11 = ((r1==cb+1) ? c0 : 0.f) - a4[3];
        *(uint32_t*)&Qg[(size_t)r0*MM + cb] = pack_bf16x2(q00,q01);
        *(uint32_t*)&Qg[(size_t)r1*MM + cb] = pack_bf16x2(q10,q11);
      }
    }
    return;
  }

  // slow path: Newton-Schulz x2 (unchanged)
  #pragma unroll 1
  for (int it=0; it<2; it++){
    __syncthreads();
    {
      float acc[16][4];
      #pragma unroll
      for (int i=0;i<16;i++)
        #pragma unroll
        for (int j=0;j<4;j++) acc[i][j]=0.f;
      mm128(sb + N_KB, sb + N_XB, wr, wc, l15, lh, acc);
      #pragma unroll
      for (int mt=0;mt<2;mt++){
        int r0 = wr*32 + mt*16 + lane4;
        int r1 = r0 + 8;
        #pragma unroll
        for (int nf=0;nf<8;nf++){
          int cb = wc*64 + nf*8 + lpair;
          float* a4 = acc[mt*8+nf];
          *(uint32_t*)(smc + N_YB + r0*KPITCH + cb*2) = pack_bf16x2(a4[0],a4[1]);
          *(uint32_t*)(smc + N_YB + r1*KPITCH + cb*2) = pack_bf16x2(a4[2],a4[3]);
        }
      }
    }
    __syncthreads();
    {
      float acc[16][4];
      #pragma unroll
      for (int i=0;i<16;i++)
        #pragma unroll
        for (int j=0;j<4;j++) acc[i][j]=0.f;
      mm128(sb + N_XB, sb + N_YB, wr, wc, l15, lh, acc);
      __syncthreads();
      float c_acc[4] = {0.f,0.f,0.f,0.f};
      #pragma unroll
      for (int mt=0;mt<2;mt++){
        int r0 = wr*32 + mt*16 + lane4;
        int r1 = r0 + 8;
        #pragma unroll
        for (int nf=0;nf<8;nf++){
          int cb = wc*64 + nf*8 + lpair;
          uint32_t p0 = *(const uint32_t*)(smc + N_XB + r0*KPITCH + cb*2);
          uint32_t p1 = *(const uint32_t*)(smc + N_XB + r1*KPITCH + cb*2);
          __nv_bfloat162 h0 = *reinterpret_cast<__nv_bfloat162*>(&p0);
          __nv_bfloat162 h1 = *reinterpret_cast<__nv_bfloat162*>(&p1);
          float* a4 = acc[mt*8+nf];
          float n00 = 2.f*__low2float(h0)  - a4[0];
          float n01 = 2.f*__high2float(h0) - a4[1];
          float n10 = 2.f*__low2float(h1)  - a4[2];
          float n11 = 2.f*__high2float(h1) - a4[3];
          *(uint32_t*)(smc + N_XB + r0*KPITCH + cb*2) = pack_bf16x2(n00,n01);
          *(uint32_t*)(smc + N_XB + r1*KPITCH + cb*2) = pack_bf16x2(n10,n11);
          if (it == 1){
            float u0 = um[cb], u1 = um[cb+1];
            c_acc[mt*2+0] += n00*u0 + n01*u1;
            c_acc[mt*2+1] += n10*u0 + n11*u1;
          }
        }
      }
      if (it == 1){
        #pragma unroll
        for (int u=0;u<4;u++){
          float v = c_acc[u];
          v += __shfl_xor_sync(0xffffffffu, v, 1);
          v += __shfl_xor_sync(0xffffffffu, v, 2);
          if ((lane & 3) == 0){
            int row = wr*32 + (u>>1)*16 + (u&1)*8 + lane4;
            pc[wc*128 + row] = v;
          }
        }
      }
    }
  }
  __syncthreads();
  if (tid < MM) g_cv[ho*MM + tid] = pc[tid] + pc[128+tid];

  {
    const float* Lv = u_tril + (size_t)o*TRILN;
    for (int it=0; it<32; it++){
      int idx = tid + it*256;
      int j = idx & 127, kp = (idx >> 7)*2;
      float v0 = (kp   >= j) ? Lv[(kp*(kp+1))/2 + j] : 0.f;
      float v1 = (kp+1 >= j) ? Lv[((kp+1)*(kp+2))/2 + j] : 0.f;
      *(uint32_t*)(smc + N_KB + j*KPITCH + kp*2) = pack_bf16x2(v0, v1);
    }
  }
  __syncthreads();

  {
    float acc[16][4];
    #pragma unroll
    for (int i=0;i<16;i++)
      #pragma unroll
      for (int j=0;j<4;j++) acc[i][j]=0.f;
    mm128(sb + N_XB, sb + N_KB, wr, wc, l15, lh, acc);
    __syncthreads();
    #pragma unroll
    for (int mt=0;mt<2;mt++){
      int r0 = wr*32 + mt*16 + lane4;
      int r1 = r0 + 8;
      #pragma unroll
      for (int nf=0;nf<8;nf++){
        int cb = wc*64 + nf*8 + lpair;
        float* a4 = acc[mt*8+nf];
        *(uint32_t*)(smc + N_YB + r0*KPITCH + cb*2) = pack_bf16x2(a4[0],a4[1]);
        *(uint32_t*)(smc + N_YB + r1*KPITCH + cb*2) = pack_bf16x2(a4[2],a4[3]);
      }
    }
  }
  __syncthreads();

  {
    float acc[16][4];
    #pragma unroll
    for (int i=0;i<16;i++)
      #pragma unroll
      for (int j=0;j<4;j++) acc[i][j]=0.f;
    mm128(sb + N_YB, sb + N_YB, wr, wc, l15, lh, acc);
    __nv_bfloat16* Qg = g_Qb + (size_t)ho*MM*MM;
    #pragma unroll
    for (int mt=0;mt<2;mt++){
      int r0 = wr*32 + mt*16 + lane4;
      int r1 = r0 + 8;
      #pragma unroll
      for (int nf=0;nf<8;nf++){
        int cb = wc*64 + nf*8 + lpair;
        uint32_t p0 = *(const uint32_t*)(smc + N_XB + r0*KPITCH + cb*2);
        uint32_t p1 = *(const uint32_t*)(smc + N_XB + r1*KPITCH + cb*2);
        __nv_bfloat162 h0 = *reinterpret_cast<__nv_bfloat162*>(&p0);
        __nv_bfloat162 h1 = *reinterpret_cast<__nv_bfloat162*>(&p1);
        float* a4 = acc[mt*8+nf];
        *(uint32_t*)&Qg[(size_t)r0*MM + cb] = pack_bf16x2(__low2float(h0)-a4[0], __high2float(h0)-a4[1]);
        *(uint32_t*)&Qg[(size_t)r1*MM + cb] = pack_bf16x2(__low2float(h1)-a4[2], __high2float(h1)-a4[3]);
      }
    }
  }
}

// ============ k_main: resident x, G=2, 4-stage z ring, exp-skip epilogue ============
#define OFF_X2   0        // 512
#define OFF_Z2   512      // 512
#define OFF_RED  1024     // 1024
#define OFF_MU   2048     // 512
#define OFF_XR   3584     // 67584 -> 71168 (rare path: kuf tile KPITCH)
#define OFF_ZR   71168    // 4*10240 = 40960 -> 112128
#define SMEM_MAIN 112128

__global__ __launch_bounds__(256,2) void k_main(float* __restrict__ out){
  extern __shared__ char smc[];
  uint32_t sb = smem_u32(smc);
  float* sx2 = (float*)(smc + OFF_X2);
  float* sz2 = (float*)(smc + OFF_Z2);
  float* red = (float*)(smc + OFF_RED);
  float* muv = (float*)(smc + OFF_MU);

  int ho0 = blockIdx.y * G;
  int h   = ho0 / NOUT;
  int b0  = blockIdx.x * MM;
  int tid = threadIdx.x;
  int wid = tid >> 5, lane = tid & 31;
  int wr = wid >> 1, wc = wid & 1;
  int l15 = lane & 15, lh = lane >> 4;
  int lane4 = lane >> 2, lpair = (lane & 3)*2;

  if (tid < MM) sx2[tid] = g_x2[h*B_SZ + b0 + tid];

  const __nv_bfloat16* xb = g_xb + ((size_t)h*B_SZ + b0)*DIN;
  float sf2 = g_sf2v[h];

  uint32_t zr_base[4];
  #pragma unroll
  for (int s=0;s<4;s++) zr_base[s] = sb + OFF_ZR + s*XSTB;
  int zr0 = tid >> 2, zq0 = tid & 3;
  int zr1 = (tid+256) >> 2, zq1 = (tid+256) & 3;

  // stage resident x + z chunks 0..2 (prefetch depth 3)
  {
    #pragma unroll
    for (int it=0; it<16; it++){
      int seg = tid + it*256;
      int r = seg >> 5, q = seg & 31;
      CP16(sb + OFF_XR + r*XP + q*16, xb + (size_t)r*DIN + q*8);
    }
    const __nv_bfloat16* zb0 = g_zb + (size_t)ho0*MM*DIN;
    #pragma unroll
    for (int s=0;s<3;s++){
      CP16(zr_base[s] + zr0*SP2 + zq0*16, zb0 + (size_t)zr0*DIN + s*32 + zq0*8);
      CP16(zr_base[s] + zr1*SP2 + zq1*16, zb0 + (size_t)zr1*DIN + s*32 + zq1*8);
      CP_COMMIT();
    }
  }

  uint32_t aoffA = (wr*32 + l15)*XP + lh*16;
  uint32_t boffA = (wc*64 + l15)*SP2 + lh*16;

  #pragma unroll 1
  for (int g=0; g<G; g++){
    int ho = ho0 + g;
    if (tid < MM) sz2[tid] = g_z2[ho*MM + tid];

    float acc[16][4];
    #pragma unroll
    for (int i=0;i<16;i++)
      #pragma unroll
      for (int j=0;j<4;j++) acc[i][j]=0.f;

    #pragma unroll 1
    for (int c=0;c<8;c++){
      int t = g*8 + c;
      CP_WAIT(2);
      __syncthreads();
      chunk32x(sb + OFF_XR + aoffA + c*64, zr_base[t%4] + boffA, acc);
      int tn = t + 3;
      if (tn < G*8){
        const __nv_bfloat16* zbn = g_zb + (size_t)(ho0 + (tn>>3))*MM*DIN;
        int cn = tn & 7;
        CP16(zr_base[tn%4] + zr0*SP2 + zq0*16, zbn + (size_t)zr0*DIN + cn*32 + zq0*8);
        CP16(zr_base[tn%4] + zr1*SP2 + zq1*16, zbn + (size_t)zr1*DIN + cn*32 + zq1*8);
      }
      CP_COMMIT();   // uniform one group per iteration
    }

    // epilogue: d2 pass + warp exp-skip vote
    float locmin = 1e30f;
    #pragma unroll
    for (int mt=0;mt<2;mt++){
      int r0 = wr*32 + mt*16 + lane4;
      int r1 = r0 + 8;
      float x20 = sx2[r0], x21 = sx2[r1];
      #pragma unroll
      for (int nf=0;nf<8;nf++){
        int cb = wc*64 + nf*8 + lpair;
        float z20 = sz2[cb], z21 = sz2[cb+1];
        float* a4 = acc[mt*8+nf];
        a4[0] = fmaxf(x20 + z20 - 2.f*a4[0], 0.f);
        a4[1] = fmaxf(x20 + z21 - 2.f*a4[1], 0.f);
        a4[2] = fmaxf(x21 + z20 - 2.f*a4[2], 0.f);
        a4[3] = fmaxf(x21 + z21 - 2.f*a4[3], 0.f);
        locmin = fminf(locmin, fminf(fminf(a4[0],a4[1]), fminf(a4[2],a4[3])));
      }
    }
    int allbig = __all_sync(0xffffffffu, locmin >= D2CUT);
    uint32_t nzbits = 0;
    if (!allbig){
      #pragma unroll
      for (int mt=0;mt<2;mt++){
        #pragma unroll
        for (int nf=0;nf<8;nf++){
          float* a4 = acc[mt*8+nf];
          a4[0] = rbf(sf2, a4[0]);
          a4[1] = rbf(sf2, a4[1]);
          a4[2] = rbf(sf2, a4[2]);
          a4[3] = rbf(sf2, a4[3]);
          nzbits |= __float_as_uint(a4[0]) | __float_as_uint(a4[1]) |
                    __float_as_uint(a4[2]) | __float_as_uint(a4[3]);
        }
      }
    }

    int any = __syncthreads_or((int)nzbits);

    if (!any){
      if (tid < MM){
        size_t base = (size_t)ho*B_SZ + b0 + tid;
        out[base] = 0.f;
        out[(size_t)HOC*B_SZ + base] = sf2;
      }
      continue;
    }

    // ================= RARE path (correct, slow; clobbers resident x) =================
    CP_WAIT(0);
    __syncthreads();
    #pragma unroll
    for (int mt=0;mt<2;mt++){
      int r0 = wr*32 + mt*16 + lane4;
      int r1 = r0 + 8;
      #pragma unroll
      for (int nf=0;nf<8;nf++){
        int cb = wc*64 + nf*8 + lpair;
        float* a4 = acc[mt*8+nf];
        uint32_t w0, w1;
        if (allbig){ w0 = 0u; w1 = 0u; }            // this warp's kuf is all zero
        else { w0 = pack_bf16x2(a4[0],a4[1]); w1 = pack_bf16x2(a4[2],a4[3]); }
        *(uint32_t*)(smc + OFF_XR + r0*KPITCH + cb*2) = w0;
        *(uint32_t*)(smc + OFF_XR + r1*KPITCH + cb*2) = w1;
      }
    }
    __syncthreads();
    {
      int r = tid >> 1, halfsel = tid & 1;
      const __nv_bfloat16* Qg = g_Qb + (size_t)ho*MM*MM;
      const float* cv = g_cv + ho*MM;
      const __nv_bfloat16* krow = (const __nv_bfloat16*)(smc + OFF_XR + r*KPITCH);
      float var_p = 0.f;
      for (int j = halfsel*64; j < halfsel*64+64; j++){
        float y = 0.f;
        const __nv_bfloat16* qrow = Qg + (size_t)j*MM;
        for (int m=0;m<MM;m++)
          y += __bfloat162float(krow[m]) * __bfloat162float(qrow[m]);
        var_p += y * __bfloat162float(krow[j]);
      }
      red[tid] = var_p;
      if (halfsel == 0){
        float mu = 0.f;
        for (int m=0;m<MM;m++) mu += cv[m]*__bfloat162float(krow[m]);
        muv[r] = mu;
      }
    }
    __syncthreads();
    if (tid < MM){
      size_t base = (size_t)ho*B_SZ + b0 + tid;
      out[base] = muv[tid];
      out[(size_t)HOC*B_SZ + base] = sf2 - (red[2*tid] + red[2*tid+1]);
    }
    __syncthreads();
    if (g+1 < G){
      #pragma unroll
      for (int it=0; it<16; it++){
        int seg = tid + it*256;
        int rr = seg >> 5, q = seg & 31;
        CP16(sb + OFF_XR + rr*XP + q*16, xb + (size_t)rr*DIN + q*8);
      }
      CP_COMMIT();
      CP_WAIT(0);
      __syncthreads();
    }
  }
}

// ---------------- launch ----------------
extern "C" void kernel_launch(void* const* d_in, const int* in_sizes, int n_in,
                              void* d_out, int out_size){
  const float* x      = (const float*)d_in[0];
  const float* z      = (const float*)d_in[1];
  const float* u_mean = (const float*)d_in[2];
  const float* u_tril = (const float*)d_in[3];
  const float* theta  = (const float*)d_in[4];
  float* out = (float*)d_out;

  cudaFuncSetAttribute(k_factor, cudaFuncAttributeMaxDynamicSharedMemorySize, N_TOT);
  cudaFuncSetAttribute(k_main,   cudaFuncAttributeMaxDynamicSharedMemorySize, SMEM_MAIN);

  k_prep<<<(NH*B_SZ + HOC*MM)/4, 256>>>(x, z, theta);
  k_factor<<<HOC, 256, N_TOT>>>(u_mean, u_tril);
  k_main<<<dim3(B_SZ/MM, HOC/G), 256, SMEM_MAIN>>>(out);
}

// round 14
// speedup vs baseline: 1.5528x; 1.1373x over previous
#include <cuda_runtime.h>
#include <cuda_bf16.h>
#include <math.h>
#include <cstdint>

#define B_SZ  4096
#define DIN   256
#define NOUT  32
#define MM    128
#define NH    2
#define HOC   (NH*NOUT)
#define JIT   1e-4f
#define TRILN (MM*(MM+1)/2)
#define D2CUT 170.0f

// ---------------- scratch ----------------
__device__ float g_sf2v[NH];
__device__ float g_x2[NH*B_SZ];
__device__ float g_z2[HOC*MM];
__device__ __align__(16) __nv_bfloat16 g_xb[NH*B_SZ*DIN];
__device__ __align__(16) __nv_bfloat16 g_zb[HOC*MM*DIN];
// per-block kuf scratch for the (never-taken) rare path: 1024 blocks x 128x128 bf16
__device__ __align__(16) __nv_bfloat16 g_kscr[1024*MM*MM];

// ---------------- helpers ----------------
__device__ __forceinline__ uint32_t smem_u32(const void* p){
  uint32_t a;
  asm("{ .reg .u64 t; cvta.to.shared.u64 t, %1; cvt.u32.u64 %0, t; }" : "=r"(a) : "l"(p));
  return a;
}
__device__ __forceinline__ void ldsm4(uint32_t addr, uint32_t* r){
  asm volatile("ldmatrix.sync.aligned.m8n8.x4.shared.b16 {%0,%1,%2,%3}, [%4];"
    : "=r"(r[0]),"=r"(r[1]),"=r"(r[2]),"=r"(r[3]) : "r"(addr));
}
__device__ __forceinline__ void mma16816(float* c, const uint32_t* a, const uint32_t* b){
  asm volatile("mma.sync.aligned.m16n8k16.row.col.f32.bf16.bf16.f32 "
    "{%0,%1,%2,%3}, {%4,%5,%6,%7}, {%8,%9}, {%0,%1,%2,%3};"
    : "+f"(c[0]),"+f"(c[1]),"+f"(c[2]),"+f"(c[3])
    : "r"(a[0]),"r"(a[1]),"r"(a[2]),"r"(a[3]), "r"(b[0]),"r"(b[1]));
}
#define CP16(dst, src) asm volatile("cp.async.cg.shared.global [%0], [%1], 16;" :: "r"(dst), "l"(src))
#define CP_COMMIT()    asm volatile("cp.async.commit_group;" ::: "memory")
#define CP_WAIT(n)     asm volatile("cp.async.wait_group %0;" :: "n"(n) : "memory")

__device__ __forceinline__ uint32_t pack_bf16x2(float lo, float hi){
  uint32_t r;
  asm("cvt.rn.satfinite.bf16x2.f32 %0, %1, %2;" : "=r"(r) : "f"(hi), "f"(lo));
  return r;
}
__device__ __forceinline__ float rbf(float sf2, float d2){
  return (d2 < D2CUT) ? sf2*__expf(-0.5f*d2) : 0.f;
}

#define SP2    80
#define XSTB   10240
#define KPITCH 272
#define XP     528
#define G      2

// 128x128x128 bf16 block GEMM from KPITCH tiles (rare-path NS)
__device__ __forceinline__ void mm128(uint32_t aBase, uint32_t bBase,
                                      int wr, int wc, int l15, int lh,
                                      float acc[16][4]){
  uint32_t aB0 = aBase + (wr*32 + l15)*KPITCH + lh*16;
  uint32_t bB0 = bBase + (wc*64 + l15)*KPITCH + lh*16;
  #pragma unroll
  for (int ks=0;ks<8;ks++){
    uint32_t af[2][4], bt[4], bfr[8][2];
    #pragma unroll
    for (int mt=0;mt<2;mt++) ldsm4(aB0 + ks*32 + mt*16*KPITCH, af[mt]);
    #pragma unroll
    for (int nn=0;nn<4;nn++){
      ldsm4(bB0 + ks*32 + nn*16*KPITCH, bt);
      bfr[nn*2][0]=bt[0]; bfr[nn*2][1]=bt[2];
      bfr[nn*2+1][0]=bt[1]; bfr[nn*2+1][1]=bt[3];
    }
    #pragma unroll
    for (int mt=0;mt<2;mt++)
      #pragma unroll
      for (int nf=0;nf<8;nf++)
        mma16816(acc[mt*8+nf], af[mt], bfr[nf]);
  }
}

// one K=32 chunk: A resident x (XP pitch), B z ring (SP2 pitch)
__device__ __forceinline__ void chunk32x(uint32_t aB, uint32_t bB, float acc[16][4]){
  #pragma unroll
  for (int ks=0;ks<2;ks++){
    uint32_t af[2][4], bt[4], bfr[8][2];
    #pragma unroll
    for (int mt=0;mt<2;mt++) ldsm4(aB + ks*32 + mt*16*XP, af[mt]);
    #pragma unroll
    for (int nn=0;nn<4;nn++){
      ldsm4(bB + ks*32 + nn*16*SP2, bt);
      bfr[nn*2][0]=bt[0]; bfr[nn*2][1]=bt[2];
      bfr[nn*2+1][0]=bt[1]; bfr[nn*2+1][1]=bt[3];
    }
    #pragma unroll
    for (int mt=0;mt<2;mt++)
      #pragma unroll
      for (int nf=0;nf<8;nf++)
        mma16816(acc[mt*8+nf], af[mt], bfr[nf]);
  }
}

// ---------------- prep (unchanged) ----------------
__global__ void k_prep(const float* __restrict__ x, const float* __restrict__ z,
                       const float* __restrict__ theta){
  __shared__ float sscal[256];
  __shared__ float sw[8];
  int tid = threadIdx.x;
  int lane = tid & 31, wid = tid >> 5;
  int row0 = blockIdx.x*4;
  int hblk = (row0 < NH*B_SZ) ? (row0 / B_SZ)
                              : ((row0 - NH*B_SZ) / (NOUT*MM));
  sscal[tid] = expf(-theta[hblk*(DIN+1) + 1 + tid]);
  if (blockIdx.x == 0 && tid < NH) g_sf2v[tid] = expf(theta[tid*(DIN+1)]);
  __syncthreads();

  int rloc = tid >> 6;
  int col  = (tid & 63) << 2;
  int row  = row0 + rloc;

  const float* src; __nv_bfloat16* dst;
  if (row < NH*B_SZ){
    int b = row - hblk*B_SZ;
    src = x + (size_t)b*DIN;
    dst = g_xb + (size_t)row*DIN;
  } else {
    int id = row - NH*B_SZ;
    int om = id % (NOUT*MM);
    src = z + (size_t)om*DIN;
    dst = g_zb + (size_t)id*DIN;
  }
  float4 xv = *(const float4*)(src + col);
  float v0 = xv.x * sscal[col];
  float v1 = xv.y * sscal[col+1];
  float v2 = xv.z * sscal[col+2];
  float v3 = xv.w * sscal[col+3];
  uint2 pk = make_uint2(pack_bf16x2(v0,v1), pack_bf16x2(v2,v3));
  *(uint2*)(dst + col) = pk;

  float p = v0*v0 + v1*v1 + v2*v2 + v3*v3;
  #pragma unroll
  for (int o=16;o;o>>=1) p += __shfl_down_sync(0xffffffffu, p, o);
  if (lane == 0) sw[wid] = p;
  __syncthreads();
  if (tid < 4){
    float t = sw[2*tid] + sw[2*tid+1];
    int r = row0 + tid;
    if (r < NH*B_SZ) g_x2[r] = t; else g_z2[r - NH*B_SZ] = t;
  }
}

// ============ k_main: resident x, G=2, 4-stage z ring, exp-skip; self-sufficient rare path ============
#define OFF_X2   0        // 512
#define OFF_Z2   512      // 512
#define OFF_XR   3584     // 67584 -> 71168
#define OFF_ZR   71168    // 4*10240 -> 112128
// rare-path overlay (clobbers XR/ZR):
#define OFF_RK   3584             // Kb  bf16 KPITCH 34816
#define OFF_RX   38400            // Xb  (-> P)      34816
#define OFF_RY   73216            // Yb              34816 -> 108032
#define SMEM_MAIN 112128

__global__ __launch_bounds__(256,2) void k_main(const float* __restrict__ u_mean,
                                                const float* __restrict__ u_tril,
                                                float* __restrict__ out){
  extern __shared__ char smc[];
  uint32_t sb = smem_u32(smc);
  float* sx2 = (float*)(smc + OFF_X2);
  float* sz2 = (float*)(smc + OFF_Z2);

  int ho0 = blockIdx.y * G;
  int h   = ho0 / NOUT;
  int b0  = blockIdx.x * MM;
  int tid = threadIdx.x;
  int wid = tid >> 5, lane = tid & 31;
  int wr = wid >> 1, wc = wid & 1;
  int l15 = lane & 15, lh = lane >> 4;
  int lane4 = lane >> 2, lpair = (lane & 3)*2;

  if (tid < MM) sx2[tid] = g_x2[h*B_SZ + b0 + tid];

  const __nv_bfloat16* xb = g_xb + ((size_t)h*B_SZ + b0)*DIN;
  float sf2 = g_sf2v[h];

  uint32_t zr_base[4];
  #pragma unroll
  for (int s=0;s<4;s++) zr_base[s] = sb + OFF_ZR + s*XSTB;
  int zr0 = tid >> 2, zq0 = tid & 3;
  int zr1 = (tid+256) >> 2, zq1 = (tid+256) & 3;

  // stage resident x + z chunks 0..2
  {
    #pragma unroll
    for (int it=0; it<16; it++){
      int seg = tid + it*256;
      int r = seg >> 5, q = seg & 31;
      CP16(sb + OFF_XR + r*XP + q*16, xb + (size_t)r*DIN + q*8);
    }
    const __nv_bfloat16* zb0 = g_zb + (size_t)ho0*MM*DIN;
    #pragma unroll
    for (int s=0;s<3;s++){
      CP16(zr_base[s] + zr0*SP2 + zq0*16, zb0 + (size_t)zr0*DIN + s*32 + zq0*8);
      CP16(zr_base[s] + zr1*SP2 + zq1*16, zb0 + (size_t)zr1*DIN + s*32 + zq1*8);
      CP_COMMIT();
    }
  }

  uint32_t aoffA = (wr*32 + l15)*XP + lh*16;
  uint32_t boffA = (wc*64 + l15)*SP2 + lh*16;

  #pragma unroll 1
  for (int g=0; g<G; g++){
    int ho = ho0 + g;
    if (tid < MM) sz2[tid] = g_z2[ho*MM + tid];

    float acc[16][4];
    #pragma unroll
    for (int i=0;i<16;i++)
      #pragma unroll
      for (int j=0;j<4;j++) acc[i][j]=0.f;

    #pragma unroll 1
    for (int c=0;c<8;c++){
      int t = g*8 + c;
      CP_WAIT(2);
      __syncthreads();
      chunk32x(sb + OFF_XR + aoffA + c*64, zr_base[t%4] + boffA, acc);
      int tn = t + 3;
      if (tn < G*8){
        const __nv_bfloat16* zbn = g_zb + (size_t)(ho0 + (tn>>3))*MM*DIN;
        int cn = tn & 7;
        CP16(zr_base[tn%4] + zr0*SP2 + zq0*16, zbn + (size_t)zr0*DIN + cn*32 + zq0*8);
        CP16(zr_base[tn%4] + zr1*SP2 + zq1*16, zbn + (size_t)zr1*DIN + cn*32 + zq1*8);
      }
      CP_COMMIT();
    }

    // epilogue: d2 pass + warp exp-skip vote
    float locmin = 1e30f;
    #pragma unroll
    for (int mt=0;mt<2;mt++){
      int r0 = wr*32 + mt*16 + lane4;
      int r1 = r0 + 8;
      float x20 = sx2[r0], x21 = sx2[r1];
      #pragma unroll
      for (int nf=0;nf<8;nf++){
        int cb = wc*64 + nf*8 + lpair;
        float z20 = sz2[cb], z21 = sz2[cb+1];
        float* a4 = acc[mt*8+nf];
        a4[0] = fmaxf(x20 + z20 - 2.f*a4[0], 0.f);
        a4[1] = fmaxf(x20 + z21 - 2.f*a4[1], 0.f);
        a4[2] = fmaxf(x21 + z20 - 2.f*a4[2], 0.f);
        a4[3] = fmaxf(x21 + z21 - 2.f*a4[3], 0.f);
        locmin = fminf(locmin, fminf(fminf(a4[0],a4[1]), fminf(a4[2],a4[3])));
      }
    }
    int allbig = __all_sync(0xffffffffu, locmin >= D2CUT);
    uint32_t nzbits = 0;
    if (!allbig){
      #pragma unroll
      for (int mt=0;mt<2;mt++){
        #pragma unroll
        for (int nf=0;nf<8;nf++){
          float* a4 = acc[mt*8+nf];
          a4[0] = rbf(sf2, a4[0]);
          a4[1] = rbf(sf2, a4[1]);
          a4[2] = rbf(sf2, a4[2]);
          a4[3] = rbf(sf2, a4[3]);
          nzbits |= __float_as_uint(a4[0]) | __float_as_uint(a4[1]) |
                    __float_as_uint(a4[2]) | __float_as_uint(a4[3]);
        }
      }
    }

    int any = __syncthreads_or((int)nzbits);

    if (!any){
      if (tid < MM){
        size_t base = (size_t)ho*B_SZ + b0 + tid;
        out[base] = 0.f;
        out[(size_t)HOC*B_SZ + base] = sf2;
      }
      continue;
    }

    // ================= RARE path (fully self-sufficient; clobbers XR/ZR) =================
    CP_WAIT(0);
    __syncthreads();
    int o = ho % NOUT;
    float dK = sf2 + JIT;
    float c0 = 1.0f / dK;

    // 1. dump kuf registers to global scratch, layout [b][m]
    {
      __nv_bfloat16* ksc = g_kscr + (size_t)(blockIdx.y*(B_SZ/MM) + blockIdx.x)*MM*MM;
      #pragma unroll
      for (int mt=0;mt<2;mt++){
        int r0 = wr*32 + mt*16 + lane4;
        int r1 = r0 + 8;
        #pragma unroll
        for (int nf=0;nf<8;nf++){
          int cb = wc*64 + nf*8 + lpair;
          float* a4 = acc[mt*8+nf];
          uint32_t w0, w1;
          if (allbig){ w0 = 0u; w1 = 0u; }
          else { w0 = pack_bf16x2(a4[0],a4[1]); w1 = pack_bf16x2(a4[2],a4[3]); }
          *(uint32_t*)&ksc[(size_t)r0*MM + cb] = w0;
          *(uint32_t*)&ksc[(size_t)r1*MM + cb] = w1;
        }
      }
    }

    // 2. build Kuu bf16 (scalar from g_zb), Xb = c0*I
    {
      const __nv_bfloat16* zrows = g_zb + (size_t)ho*MM*DIN;
      for (int idx = tid; idx < MM*MM; idx += 256){
        int i = idx >> 7, j = idx & 127;
        float dot = 0.f;
        const __nv_bfloat16* zi = zrows + (size_t)i*DIN;
        const __nv_bfloat16* zj = zrows + (size_t)j*DIN;
        for (int d=0; d<DIN; d++)
          dot += __bfloat162float(zi[d]) * __bfloat162float(zj[d]);
        float d2 = fmaxf(g_z2[ho*MM+i] + g_z2[ho*MM+j] - 2.f*dot, 0.f);
        float kv = (i==j) ? dK : rbf(sf2, d2);
        ((__nv_bfloat16*)(smc + OFF_RK + i*KPITCH))[j] = __float2bfloat16(kv);
        ((__nv_bfloat16*)(smc + OFF_RX + i*KPITCH))[j] = __float2bfloat16((i==j) ? c0 : 0.f);
      }
    }
    __syncthreads();

    // 3. Newton-Schulz x2 (tensor): Y = K X ; X <- 2X - X Y^T  (X,K commute)
    #pragma unroll 1
    for (int it=0; it<2; it++){
      {
        float a2[16][4];
        #pragma unroll
        for (int i=0;i<16;i++)
          #pragma unroll
          for (int j=0;j<4;j++) a2[i][j]=0.f;
        mm128(sb + OFF_RK, sb + OFF_RX, wr, wc, l15, lh, a2);
        #pragma unroll
        for (int mt=0;mt<2;mt++){
          int r0 = wr*32 + mt*16 + lane4;
          int r1 = r0 + 8;
          #pragma unroll
          for (int nf=0;nf<8;nf++){
            int cb = wc*64 + nf*8 + lpair;
            float* a4 = a2[mt*8+nf];
            *(uint32_t*)(smc + OFF_RY + r0*KPITCH + cb*2) = pack_bf16x2(a4[0],a4[1]);
            *(uint32_t*)(smc + OFF_RY + r1*KPITCH + cb*2) = pack_bf16x2(a4[2],a4[3]);
          }
        }
      }
      __syncthreads();
      {
        float a2[16][4];
        #pragma unroll
        for (int i=0;i<16;i++)
          #pragma unroll
          for (int j=0;j<4;j++) a2[i][j]=0.f;
        mm128(sb + OFF_RX, sb + OFF_RY, wr, wc, l15, lh, a2);
        __syncthreads();
        #pragma unroll
        for (int mt=0;mt<2;mt++){
          int r0 = wr*32 + mt*16 + lane4;
          int r1 = r0 + 8;
          #pragma unroll
          for (int nf=0;nf<8;nf++){
            int cb = wc*64 + nf*8 + lpair;
            uint32_t p0 = *(const uint32_t*)(smc + OFF_RX + r0*KPITCH + cb*2);
            uint32_t p1 = *(const uint32_t*)(smc + OFF_RX + r1*KPITCH + cb*2);
            __nv_bfloat162 h0 = *reinterpret_cast<__nv_bfloat162*>(&p0);
            __nv_bfloat162 h1 = *reinterpret_cast<__nv_bfloat162*>(&p1);
            float* a4 = a2[mt*8+nf];
            *(uint32_t*)(smc + OFF_RX + r0*KPITCH + cb*2) =
              pack_bf16x2(2.f*__low2float(h0)-a4[0], 2.f*__high2float(h0)-a4[1]);
            *(uint32_t*)(smc + OFF_RX + r1*KPITCH + cb*2) =
              pack_bf16x2(2.f*__low2float(h1)-a4[2], 2.f*__high2float(h1)-a4[3]);
          }
        }
      }
      __syncthreads();
    }

    // 4. scalar apply per column b (threads 0..127): P = Xb tile
    if (tid < MM){
      const __nv_bfloat16* ksc = g_kscr + (size_t)(blockIdx.y*(B_SZ/MM) + blockIdx.x)*MM*MM
                               + (size_t)tid*MM;            // kuf column (b = tid)
      const float* Lv = u_tril + (size_t)o*TRILN;
      const float* um = u_mean + o*MM;
      float w[MM];
      for (int m=0;m<MM;m++){
        const __nv_bfloat16* prow = (const __nv_bfloat16*)(smc + OFF_RX + m*KPITCH);
        float s = 0.f;
        for (int k=0;k<MM;k++) s += __bfloat162float(prow[k]) * __bfloat162float(ksc[k]);
        w[m] = s;
      }
      float diag1 = 0.f, mu = 0.f;
      for (int m=0;m<MM;m++){
        diag1 += w[m]*__bfloat162float(ksc[m]);
        mu    += w[m]*um[m];
      }
      float diag2 = 0.f;
      for (int j=0;j<MM;j++){
        float u = 0.f;
        for (int k=j;k<MM;k++) u += Lv[(k*(k+1))/2 + j] * w[k];
        diag2 += u*u;
      }
      size_t base = (size_t)ho*B_SZ + b0 + tid;
      out[base] = mu;
      out[(size_t)HOC*B_SZ + base] = sf2 - diag1 + diag2;
    }
    __syncthreads();

    // 5. restore resident x + z ring + sx2 for remaining groups
    if (g+1 < G){
      if (tid < MM) sx2[tid] = g_x2[h*B_SZ + b0 + tid];
      #pragma unroll
      for (int it=0; it<16; it++){
        int seg = tid + it*256;
        int rr = seg >> 5, q = seg & 31;
        CP16(sb + OFF_XR + rr*XP + q*16, xb + (size_t)rr*DIN + q*8);
      }
      const __nv_bfloat16* zbn = g_zb + (size_t)(ho0+g+1)*MM*DIN;
      int base_t = (g+1)*8;
      #pragma unroll
      for (int s=0;s<3;s++){
        int t = base_t + s;
        CP16(zr_base[t%4] + zr0*SP2 + zq0*16, zbn + (size_t)zr0*DIN + s*32 + zq0*8);
        CP16(zr_base[t%4] + zr1*SP2 + zq1*16, zbn + (size_t)zr1*DIN + s*32 + zq1*8);
        CP_COMMIT();
      }
      // mainloop for next group expects 3 outstanding groups; it CP_WAITs(2) first. ok.
      // but it also issues its own prefetches starting at t+3; indices line up since we
      // prefetched chunks t = base_t..base_t+2 into rings (t%4).
      // NOTE: the next-group loop starts at c=0 => t=base_t, CP_WAIT(2) sees these 3 groups.
      // x staging group: fold into first commit above? x CP16s were issued before first commit,
      // so group(base_t) includes x. Wait(2) at c=0 drains it. correct.
    }
  }
}

// ---------------- launch ----------------
extern "C" void kernel_launch(void* const* d_in, const int* in_sizes, int n_in,
                              void* d_out, int out_size){
  const float* x      = (const float*)d_in[0];
  const float* z      = (const float*)d_in[1];
  const float* u_mean = (const float*)d_in[2];
  const float* u_tril = (const float*)d_in[3];
  const float* theta  = (const float*)d_in[4];
  float* out = (float*)d_out;

  cudaFuncSetAttribute(k_main, cudaFuncAttributeMaxDynamicSharedMemorySize, SMEM_MAIN);

  k_prep<<<(NH*B_SZ + HOC*MM)/4, 256>>>(x, z, theta);
  k_main<<<dim3(B_SZ/MM, HOC/G), 256, SMEM_MAIN>>>(u_mean, u_tril, out);
}

// round 15
// speedup vs baseline: 1.7275x; 1.1125x over previous
#include <cuda_runtime.h>
#include <cuda_bf16.h>
#include <math.h>
#include <cstdint>

#define B_SZ  4096
#define DIN   256
#define NOUT  32
#define MM    128
#define NH    2
#define HOC   (NH*NOUT)
#define JIT   1e-4f
#define TRILN (MM*(MM+1)/2)
#define D2CUT 170.0f

// ---------------- scratch ----------------
__device__ float g_sf2v[NH];
__device__ float g_x2[NH*B_SZ];
__device__ float g_z2[HOC*MM];
__device__ __align__(16) __nv_bfloat16 g_xb[NH*B_SZ*DIN];
__device__ __align__(16) __nv_bfloat16 g_zb[HOC*MM*DIN];
__device__ __align__(16) __nv_bfloat16 g_kscr[1024*MM*MM];  // rare-path kuf scratch

// ---------------- helpers ----------------
__device__ __forceinline__ uint32_t smem_u32(const void* p){
  uint32_t a;
  asm("{ .reg .u64 t; cvta.to.shared.u64 t, %1; cvt.u32.u64 %0, t; }" : "=r"(a) : "l"(p));
  return a;
}
__device__ __forceinline__ void ldsm4(uint32_t addr, uint32_t* r){
  asm volatile("ldmatrix.sync.aligned.m8n8.x4.shared.b16 {%0,%1,%2,%3}, [%4];"
    : "=r"(r[0]),"=r"(r[1]),"=r"(r[2]),"=r"(r[3]) : "r"(addr));
}
__device__ __forceinline__ void mma16816(float* c, const uint32_t* a, const uint32_t* b){
  asm volatile("mma.sync.aligned.m16n8k16.row.col.f32.bf16.bf16.f32 "
    "{%0,%1,%2,%3}, {%4,%5,%6,%7}, {%8,%9}, {%0,%1,%2,%3};"
    : "+f"(c[0]),"+f"(c[1]),"+f"(c[2]),"+f"(c[3])
    : "r"(a[0]),"r"(a[1]),"r"(a[2]),"r"(a[3]), "r"(b[0]),"r"(b[1]));
}
#define CP16(dst, src) asm volatile("cp.async.cg.shared.global [%0], [%1], 16;" :: "r"(dst), "l"(src))
#define CP_COMMIT()    asm volatile("cp.async.commit_group;" ::: "memory")
#define CP_WAIT(n)     asm volatile("cp.async.wait_group %0;" :: "n"(n) : "memory")

__device__ __forceinline__ uint32_t pack_bf16x2(float lo, float hi){
  uint32_t r;
  asm("cvt.rn.satfinite.bf16x2.f32 %0, %1, %2;" : "=r"(r) : "f"(hi), "f"(lo));
  return r;
}
__device__ __forceinline__ float rbf(float sf2, float d2){
  return (d2 < D2CUT) ? sf2*__expf(-0.5f*d2) : 0.f;
}

#define SP64   144      // K=64 stage pitch bytes (128 B data + 16 B pad)
#define ZST64  18432    // one K=64 z stage: 128*144
#define KPITCH 272
#define XP     528
#define G      2

// 128x128x128 bf16 block GEMM from KPITCH tiles (rare-path NS)
__device__ __forceinline__ void mm128(uint32_t aBase, uint32_t bBase,
                                      int wr, int wc, int l15, int lh,
                                      float acc[16][4]){
  uint32_t aB0 = aBase + (wr*32 + l15)*KPITCH + lh*16;
  uint32_t bB0 = bBase + (wc*64 + l15)*KPITCH + lh*16;
  #pragma unroll
  for (int ks=0;ks<8;ks++){
    uint32_t af[2][4], bt[4], bfr[8][2];
    #pragma unroll
    for (int mt=0;mt<2;mt++) ldsm4(aB0 + ks*32 + mt*16*KPITCH, af[mt]);
    #pragma unroll
    for (int nn=0;nn<4;nn++){
      ldsm4(bB0 + ks*32 + nn*16*KPITCH, bt);
      bfr[nn*2][0]=bt[0]; bfr[nn*2][1]=bt[2];
      bfr[nn*2+1][0]=bt[1]; bfr[nn*2+1][1]=bt[3];
    }
    #pragma unroll
    for (int mt=0;mt<2;mt++)
      #pragma unroll
      for (int nf=0;nf<8;nf++)
        mma16816(acc[mt*8+nf], af[mt], bfr[nf]);
  }
}

// one K=64 chunk: A resident x (XP pitch, col offset coff bytes), B z stage (SP64 pitch)
__device__ __forceinline__ void chunk64x(uint32_t aB, uint32_t bB, float acc[16][4]){
  #pragma unroll
  for (int ks=0;ks<4;ks++){
    uint32_t af[2][4], bt[4], bfr[8][2];
    #pragma unroll
    for (int mt=0;mt<2;mt++) ldsm4(aB + ks*32 + mt*16*XP, af[mt]);
    #pragma unroll
    for (int nn=0;nn<4;nn++){
      ldsm4(bB + ks*32 + nn*16*SP64, bt);
      bfr[nn*2][0]=bt[0]; bfr[nn*2][1]=bt[2];
      bfr[nn*2+1][0]=bt[1]; bfr[nn*2+1][1]=bt[3];
    }
    #pragma unroll
    for (int mt=0;mt<2;mt++)
      #pragma unroll
      for (int nf=0;nf<8;nf++)
        mma16816(acc[mt*8+nf], af[mt], bfr[nf]);
  }
}

// ---------------- prep (unchanged) ----------------
__global__ void k_prep(const float* __restrict__ x, const float* __restrict__ z,
                       const float* __restrict__ theta){
  __shared__ float sscal[256];
  __shared__ float sw[8];
  int tid = threadIdx.x;
  int lane = tid & 31, wid = tid >> 5;
  int row0 = blockIdx.x*4;
  int hblk = (row0 < NH*B_SZ) ? (row0 / B_SZ)
                              : ((row0 - NH*B_SZ) / (NOUT*MM));
  sscal[tid] = expf(-theta[hblk*(DIN+1) + 1 + tid]);
  if (blockIdx.x == 0 && tid < NH) g_sf2v[tid] = expf(theta[tid*(DIN+1)]);
  __syncthreads();

  int rloc = tid >> 6;
  int col  = (tid & 63) << 2;
  int row  = row0 + rloc;

  const float* src; __nv_bfloat16* dst;
  if (row < NH*B_SZ){
    int b = row - hblk*B_SZ;
    src = x + (size_t)b*DIN;
    dst = g_xb + (size_t)row*DIN;
  } else {
    int id = row - NH*B_SZ;
    int om = id % (NOUT*MM);
    src = z + (size_t)om*DIN;
    dst = g_zb + (size_t)id*DIN;
  }
  float4 xv = *(const float4*)(src + col);
  float v0 = xv.x * sscal[col];
  float v1 = xv.y * sscal[col+1];
  float v2 = xv.z * sscal[col+2];
  float v3 = xv.w * sscal[col+3];
  uint2 pk = make_uint2(pack_bf16x2(v0,v1), pack_bf16x2(v2,v3));
  *(uint2*)(dst + col) = pk;

  float p = v0*v0 + v1*v1 + v2*v2 + v3*v3;
  #pragma unroll
  for (int o=16;o;o>>=1) p += __shfl_down_sync(0xffffffffu, p, o);
  if (lane == 0) sw[wid] = p;
  __syncthreads();
  if (tid < 4){
    float t = sw[2*tid] + sw[2*tid+1];
    int r = row0 + tid;
    if (r < NH*B_SZ) g_x2[r] = t; else g_z2[r - NH*B_SZ] = t;
  }
}

// ============ k_main: resident x, G=2, K=64 chunks, 2-stage z ring ============
#define OFF_X2   0        // 512
#define OFF_Z2   512      // 512
#define OFF_XR   3584     // 67584 -> 71168
#define OFF_ZR   71168    // 2*18432 = 36864 -> 108032
// rare-path overlay (clobbers XR/ZR):
#define OFF_RK   3584
#define OFF_RX   38400
#define OFF_RY   73216    // -> 108032
#define SMEM_MAIN 108032

__global__ __launch_bounds__(256,2) void k_main(const float* __restrict__ u_mean,
                                                const float* __restrict__ u_tril,
                                                float* __restrict__ out){
  extern __shared__ char smc[];
  uint32_t sb = smem_u32(smc);
  float* sx2 = (float*)(smc + OFF_X2);
  float* sz2 = (float*)(smc + OFF_Z2);

  int ho0 = blockIdx.y * G;
  int h   = ho0 / NOUT;
  int b0  = blockIdx.x * MM;
  int tid = threadIdx.x;
  int wid = tid >> 5, lane = tid & 31;
  int wr = wid >> 1, wc = wid & 1;
  int l15 = lane & 15, lh = lane >> 4;
  int lane4 = lane >> 2, lpair = (lane & 3)*2;

  if (tid < MM) sx2[tid] = g_x2[h*B_SZ + b0 + tid];

  const __nv_bfloat16* xb = g_xb + ((size_t)h*B_SZ + b0)*DIN;
  float sf2 = g_sf2v[h];

  uint32_t zr_base[2] = { sb + OFF_ZR, sb + OFF_ZR + ZST64 };
  // z stage fill: 1024 16B segments / 256 thr = 4 per thread
  int zrow = tid >> 1, zq0 = (tid & 1)*4;   // 4 consecutive segments per thread? use (row, q) pairs:
  // simpler mapping: thread covers segs tid, tid+256, tid+512, tid+768
  // seg s -> row = s>>3, q = s&7

  // stage resident x + z chunk 0 (one commit), then z chunk 1 (second commit)
  {
    #pragma unroll
    for (int it=0; it<16; it++){
      int seg = tid + it*256;
      int r = seg >> 5, q = seg & 31;
      CP16(sb + OFF_XR + r*XP + q*16, xb + (size_t)r*DIN + q*8);
    }
    const __nv_bfloat16* zb0 = g_zb + (size_t)ho0*MM*DIN;
    #pragma unroll
    for (int it=0; it<4; it++){
      int seg = tid + it*256;
      int r = seg >> 3, q = seg & 7;
      CP16(zr_base[0] + r*SP64 + q*16, zb0 + (size_t)r*DIN + q*8);
    }
    CP_COMMIT();   // group: x + chunk0
  }

  uint32_t aoffA = (wr*32 + l15)*XP + lh*16;
  uint32_t boffA = (wc*64 + l15)*SP64 + lh*16;

  #pragma unroll 1
  for (int g=0; g<G; g++){
    int ho = ho0 + g;
    if (tid < MM) sz2[tid] = g_z2[ho*MM + tid];

    float acc[16][4];
    #pragma unroll
    for (int i=0;i<16;i++)
      #pragma unroll
      for (int j=0;j<4;j++) acc[i][j]=0.f;

    #pragma unroll 1
    for (int c=0;c<4;c++){
      int t = g*4 + c;
      // prefetch chunk t+1 into stage (t+1)%2 (safe: all warps past t-1 via last barrier)
      int tn = t + 1;
      if (tn < G*4){
        const __nv_bfloat16* zbn = g_zb + (size_t)(ho0 + (tn>>2))*MM*DIN + (size_t)(tn&3)*64;
        #pragma unroll
        for (int it=0; it<4; it++){
          int seg = tid + it*256;
          int r = seg >> 3, q = seg & 7;
          CP16(zr_base[tn&1] + r*SP64 + q*16, zbn + (size_t)r*DIN + q*8);
        }
      }
      CP_COMMIT();
      CP_WAIT(1);           // chunk t (and x on t=0) arrived
      __syncthreads();
      chunk64x(sb + OFF_XR + aoffA + c*128, zr_base[t&1] + boffA, acc);
    }

    // epilogue: d2 pass + warp exp-skip vote
    float locmin = 1e30f;
    #pragma unroll
    for (int mt=0;mt<2;mt++){
      int r0 = wr*32 + mt*16 + lane4;
      int r1 = r0 + 8;
      float x20 = sx2[r0], x21 = sx2[r1];
      #pragma unroll
      for (int nf=0;nf<8;nf++){
        int cb = wc*64 + nf*8 + lpair;
        float z20 = sz2[cb], z21 = sz2[cb+1];
        float* a4 = acc[mt*8+nf];
        a4[0] = fmaxf(x20 + z20 - 2.f*a4[0], 0.f);
        a4[1] = fmaxf(x20 + z21 - 2.f*a4[1], 0.f);
        a4[2] = fmaxf(x21 + z20 - 2.f*a4[2], 0.f);
        a4[3] = fmaxf(x21 + z21 - 2.f*a4[3], 0.f);
        locmin = fminf(locmin, fminf(fminf(a4[0],a4[1]), fminf(a4[2],a4[3])));
      }
    }
    int allbig = __all_sync(0xffffffffu, locmin >= D2CUT);
    uint32_t nzbits = 0;
    if (!allbig){
      #pragma unroll
      for (int mt=0;mt<2;mt++){
        #pragma unroll
        for (int nf=0;nf<8;nf++){
          float* a4 = acc[mt*8+nf];
          a4[0] = rbf(sf2, a4[0]);
          a4[1] = rbf(sf2, a4[1]);
          a4[2] = rbf(sf2, a4[2]);
          a4[3] = rbf(sf2, a4[3]);
          nzbits |= __float_as_uint(a4[0]) | __float_as_uint(a4[1]) |
                    __float_as_uint(a4[2]) | __float_as_uint(a4[3]);
        }
      }
    }

    int any = __syncthreads_or((int)nzbits);

    if (!any){
      if (tid < MM){
        size_t base = (size_t)ho*B_SZ + b0 + tid;
        out[base] = 0.f;
        out[(size_t)HOC*B_SZ + base] = sf2;
      }
      continue;
    }

    // ================= RARE path (self-sufficient; clobbers XR/ZR) =================
    CP_WAIT(0);
    __syncthreads();
    int o = ho % NOUT;
    float dK = sf2 + JIT;
    float c0 = 1.0f / dK;

    // 1. dump kuf to global scratch, layout [b][m]
    {
      __nv_bfloat16* ksc = g_kscr + (size_t)(blockIdx.y*(B_SZ/MM) + blockIdx.x)*MM*MM;
      #pragma unroll
      for (int mt=0;mt<2;mt++){
        int r0 = wr*32 + mt*16 + lane4;
        int r1 = r0 + 8;
        #pragma unroll
        for (int nf=0;nf<8;nf++){
          int cb = wc*64 + nf*8 + lpair;
          float* a4 = acc[mt*8+nf];
          uint32_t w0, w1;
          if (allbig){ w0 = 0u; w1 = 0u; }
          else { w0 = pack_bf16x2(a4[0],a4[1]); w1 = pack_bf16x2(a4[2],a4[3]); }
          *(uint32_t*)&ksc[(size_t)r0*MM + cb] = w0;
          *(uint32_t*)&ksc[(size_t)r1*MM + cb] = w1;
        }
      }
    }

    // 2. build Kuu bf16 (scalar), Xb = c0*I
    {
      const __nv_bfloat16* zrows = g_zb + (size_t)ho*MM*DIN;
      for (int idx = tid; idx < MM*MM; idx += 256){
        int i = idx >> 7, j = idx & 127;
        float dot = 0.f;
        const __nv_bfloat16* zi = zrows + (size_t)i*DIN;
        const __nv_bfloat16* zj = zrows + (size_t)j*DIN;
        for (int d=0; d<DIN; d++)
          dot += __bfloat162float(zi[d]) * __bfloat162float(zj[d]);
        float d2 = fmaxf(g_z2[ho*MM+i] + g_z2[ho*MM+j] - 2.f*dot, 0.f);
        float kv = (i==j) ? dK : rbf(sf2, d2);
        ((__nv_bfloat16*)(smc + OFF_RK + i*KPITCH))[j] = __float2bfloat16(kv);
        ((__nv_bfloat16*)(smc + OFF_RX + i*KPITCH))[j] = __float2bfloat16((i==j) ? c0 : 0.f);
      }
    }
    __syncthreads();

    // 3. Newton-Schulz x2 (tensor)
    #pragma unroll 1
    for (int it=0; it<2; it++){
      {
        float a2[16][4];
        #pragma unroll
        for (int i=0;i<16;i++)
          #pragma unroll
          for (int j=0;j<4;j++) a2[i][j]=0.f;
        mm128(sb + OFF_RK, sb + OFF_RX, wr, wc, l15, lh, a2);
        #pragma unroll
        for (int mt=0;mt<2;mt++){
          int r0 = wr*32 + mt*16 + lane4;
          int r1 = r0 + 8;
          #pragma unroll
          for (int nf=0;nf<8;nf++){
            int cb = wc*64 + nf*8 + lpair;
            float* a4 = a2[mt*8+nf];
            *(uint32_t*)(smc + OFF_RY + r0*KPITCH + cb*2) = pack_bf16x2(a4[0],a4[1]);
            *(uint32_t*)(smc + OFF_RY + r1*KPITCH + cb*2) = pack_bf16x2(a4[2],a4[3]);
          }
        }
      }
      __syncthreads();
      {
        float a2[16][4];
        #pragma unroll
        for (int i=0;i<16;i++)
          #pragma unroll
          for (int j=0;j<4;j++) a2[i][j]=0.f;
        mm128(sb + OFF_RX, sb + OFF_RY, wr, wc, l15, lh, a2);
        __syncthreads();
        #pragma unroll
        for (int mt=0;mt<2;mt++){
          int r0 = wr*32 + mt*16 + lane4;
          int r1 = r0 + 8;
          #pragma unroll
          for (int nf=0;nf<8;nf++){
            int cb = wc*64 + nf*8 + lpair;
            uint32_t p0 = *(const uint32_t*)(smc + OFF_RX + r0*KPITCH + cb*2);
            uint32_t p1 = *(const uint32_t*)(smc + OFF_RX + r1*KPITCH + cb*2);
            __nv_bfloat162 h0 = *reinterpret_cast<__nv_bfloat162*>(&p0);
            __nv_bfloat162 h1 = *reinterpret_cast<__nv_bfloat162*>(&p1);
            float* a4 = a2[mt*8+nf];
            *(uint32_t*)(smc + OFF_RX + r0*KPITCH + cb*2) =
              pack_bf16x2(2.f*__low2float(h0)-a4[0], 2.f*__high2float(h0)-a4[1]);
            *(uint32_t*)(smc + OFF_RX + r1*KPITCH + cb*2) =
              pack_bf16x2(2.f*__low2float(h1)-a4[2], 2.f*__high2float(h1)-a4[3]);
          }
        }
      }
      __syncthreads();
    }

    // 4. scalar apply per column b
    if (tid < MM){
      const __nv_bfloat16* ksc = g_kscr + (size_t)(blockIdx.y*(B_SZ/MM) + blockIdx.x)*MM*MM
                               + (size_t)tid*MM;
      const float* Lv = u_tril + (size_t)o*TRILN;
      const float* um = u_mean + o*MM;
      float w[MM];
      for (int m=0;m<MM;m++){
        const __nv_bfloat16* prow = (const __nv_bfloat16*)(smc + OFF_RX + m*KPITCH);
        float s = 0.f;
        for (int k=0;k<MM;k++) s += __bfloat162float(prow[k]) * __bfloat162float(ksc[k]);
        w[m] = s;
      }
      float diag1 = 0.f, mu = 0.f;
      for (int m=0;m<MM;m++){
        diag1 += w[m]*__bfloat162float(ksc[m]);
        mu    += w[m]*um[m];
      }
      float diag2 = 0.f;
      for (int j=0;j<MM;j++){
        float u = 0.f;
        for (int k=j;k<MM;k++) u += Lv[(k*(k+1))/2 + j] * w[k];
        diag2 += u*u;
      }
      size_t base = (size_t)ho*B_SZ + b0 + tid;
      out[base] = mu;
      out[(size_t)HOC*B_SZ + base] = sf2 - diag1 + diag2;
    }
    __syncthreads();

    // 5. restore resident x + z chunk for next group (matches mainloop pattern)
    if (g+1 < G){
      if (tid < MM) sx2[tid] = g_x2[h*B_SZ + b0 + tid];
      #pragma unroll
      for (int it=0; it<16; it++){
        int seg = tid + it*256;
        int rr = seg >> 5, q = seg & 31;
        CP16(sb + OFF_XR + rr*XP + q*16, xb + (size_t)rr*DIN + q*8);
      }
      int t0 = (g+1)*4;
      const __nv_bfloat16* zbn = g_zb + (size_t)(ho0+g+1)*MM*DIN;
      #pragma unroll
      for (int it=0; it<4; it++){
        int seg = tid + it*256;
        int r = seg >> 3, q = seg & 7;
        CP16(zr_base[t0&1] + r*SP64 + q*16, zbn + (size_t)r*DIN + q*8);
      }
      CP_COMMIT();   // x + chunk t0 as one group; next iter's commit+wait(1) drains it
    }
  }
}

// ---------------- launch ----------------
extern "C" void kernel_launch(void* const* d_in, const int* in_sizes, int n_in,
                              void* d_out, int out_size){
  const float* x      = (const float*)d_in[0];
  const float* z      = (const float*)d_in[1];
  const float* u_mean = (const float*)d_in[2];
  const float* u_tril = (const float*)d_in[3];
  const float* theta  = (const float*)d_in[4];
  float* out = (float*)d_out;

  cudaFuncSetAttribute(k_main, cudaFuncAttributeMaxDynamicSharedMemorySize, SMEM_MAIN);

  k_prep<<<(NH*B_SZ + HOC*MM)/4, 256>>>(x, z, theta);
  k_main<<<dim3(B_SZ/MM, HOC/G), 256, SMEM_MAIN>>>(u_mean, u_tril, out);
}